// round 5
// baseline (speedup 1.0000x reference)
#include <cuda_runtime.h>
#include <cuda_bf16.h>
#include <cstdio>

// ---------------- problem constants ----------------
#define BB   2
#define LL   2048
#define DD   2048
#define HV   32
#define HK   16
#define DK   128
#define DV   128
#define KCONV 4
#define KEY_DIM  2048
#define VAL_DIM  4096
#define CONV_DIM 8192
#define MROWS (BB*LL)          // 4096

// ---------------- scratch (static device globals; no runtime alloc) ----------------
__device__ float g_mixed[(size_t)MROWS * CONV_DIM];   // pre-conv qkv mix  (128 MB)
__device__ float g_conv [(size_t)MROWS * CONV_DIM];   // post conv+silu    (128 MB)
__device__ float g_z    [(size_t)MROWS * VAL_DIM];    // gate              (64 MB)
__device__ float g_core [(size_t)MROWS * VAL_DIM];    // scan output / gated (64 MB)
__device__ float g_qn   [(size_t)MROWS * HK * DK];    // normalized q      (32 MB)
__device__ float g_kn   [(size_t)MROWS * HK * DK];    // normalized k      (32 MB)
__device__ float g_bv   [(size_t)MROWS * HV];
__device__ float g_av   [(size_t)MROWS * HV];
__device__ float g_beta [(size_t)MROWS * HV];
__device__ float g_g    [(size_t)MROWS * HV];

// ---------------- tiled SGEMM: C[M,N] = A[M,K] @ B[K,N], all row-major ----------------
__global__ void __launch_bounds__(256) sgemm128(
    const float* __restrict__ A, const float* __restrict__ Bm,
    float* __restrict__ C, int M, int N, int K)
{
    __shared__ __align__(16) float As[8][128];
    __shared__ __align__(16) float Bs[8][128];

    const int tid = threadIdx.x;
    const int bm = blockIdx.y * 128;
    const int bn = blockIdx.x * 128;
    const int tm = (tid / 16) * 8;
    const int tn = (tid % 16) * 8;

    const int arow = tid >> 1;          // 0..127
    const int acol = (tid & 1) * 4;     // 0 or 4
    const int brow = tid >> 5;          // 0..7
    const int bcol = (tid & 31) * 4;    // 0..124

    const float* Aptr = A + (size_t)(bm + arow) * K + acol;
    const float* Bptr = Bm + (size_t)brow * N + bn + bcol;

    float acc[8][8];
    #pragma unroll
    for (int i = 0; i < 8; i++)
        #pragma unroll
        for (int j = 0; j < 8; j++) acc[i][j] = 0.f;

    for (int k0 = 0; k0 < K; k0 += 8) {
        float4 av = *(const float4*)Aptr;
        float4 bv = *(const float4*)Bptr;
        As[acol + 0][arow] = av.x;
        As[acol + 1][arow] = av.y;
        As[acol + 2][arow] = av.z;
        As[acol + 3][arow] = av.w;
        *(float4*)&Bs[brow][bcol] = bv;
        __syncthreads();

        #pragma unroll
        for (int kk = 0; kk < 8; kk++) {
            float a[8], b[8];
            *(float4*)(a)     = *(const float4*)&As[kk][tm];
            *(float4*)(a + 4) = *(const float4*)&As[kk][tm + 4];
            *(float4*)(b)     = *(const float4*)&Bs[kk][tn];
            *(float4*)(b + 4) = *(const float4*)&Bs[kk][tn + 4];
            #pragma unroll
            for (int i = 0; i < 8; i++)
                #pragma unroll
                for (int j = 0; j < 8; j++)
                    acc[i][j] = fmaf(a[i], b[j], acc[i][j]);
        }
        __syncthreads();
        Aptr += 8;
        Bptr += (size_t)8 * N;
    }

    #pragma unroll
    for (int i = 0; i < 8; i++) {
        float4 v0 = make_float4(acc[i][0], acc[i][1], acc[i][2], acc[i][3]);
        float4 v1 = make_float4(acc[i][4], acc[i][5], acc[i][6], acc[i][7]);
        float* crow = C + (size_t)(bm + tm + i) * N + bn + tn;
        *(float4*)(crow)     = v0;
        *(float4*)(crow + 4) = v1;
    }
}

// ---------------- skinny GEMM: b = H@W_b, a = H@W_a (N=32 each) ----------------
__global__ void __launch_bounds__(64) gemm_ba(
    const float* __restrict__ H, const float* __restrict__ Wb,
    const float* __restrict__ Wa, float* __restrict__ ob, float* __restrict__ oa)
{
    const int m0 = blockIdx.x * 8;
    const int t  = threadIdx.x;
    const float* W = (t < 32) ? Wb : Wa;
    const int colw = t & 31;

    float s[8];
    #pragma unroll
    for (int r = 0; r < 8; r++) s[r] = 0.f;

    for (int k = 0; k < DD; k++) {
        float wv = W[(size_t)k * 32 + colw];
        #pragma unroll
        for (int r = 0; r < 8; r++)
            s[r] = fmaf(H[(size_t)(m0 + r) * DD + k], wv, s[r]);
    }
    #pragma unroll
    for (int r = 0; r < 8; r++) {
        if (t < 32) ob[(size_t)(m0 + r) * 32 + colw] = s[r];
        else        oa[(size_t)(m0 + r) * 32 + colw] = s[r];
    }
}

// ---------------- causal depthwise conv (K=4) + SiLU ----------------
__global__ void __launch_bounds__(256) conv_silu(
    const float* __restrict__ x, const float* __restrict__ w, float* __restrict__ y)
{
    const size_t idx = (size_t)blockIdx.x * 256 + threadIdx.x; // < MROWS*CONV_DIM
    const int c = (int)(idx & (CONV_DIM - 1));
    const int l = (int)((idx >> 13) & (LL - 1));
    float4 wv = ((const float4*)w)[c];
    float acc = wv.w * x[idx];
    if (l >= 1) acc = fmaf(wv.z, x[idx - CONV_DIM], acc);
    if (l >= 2) acc = fmaf(wv.y, x[idx - 2 * CONV_DIM], acc);
    if (l >= 3) acc = fmaf(wv.x, x[idx - 3 * CONV_DIM], acc);
    y[idx] = acc / (1.f + __expf(-acc));
}

// ---------------- q/k l2norm (+ q scale) ----------------
__global__ void __launch_bounds__(256) qk_norm(
    const float* __restrict__ conv, float* __restrict__ qn, float* __restrict__ kn)
{
    const int warp = (blockIdx.x * 256 + threadIdx.x) >> 5; // row over MROWS*HK
    const int lane = threadIdx.x & 31;
    const int bl = warp >> 4;
    const int kh = warp & 15;

    const float* qp = conv + (size_t)bl * CONV_DIM + kh * DK + lane * 4;
    const float* kp = qp + KEY_DIM;
    float4 q4 = *(const float4*)qp;
    float4 k4 = *(const float4*)kp;
    float sq = q4.x*q4.x + q4.y*q4.y + q4.z*q4.z + q4.w*q4.w;
    float sk = k4.x*k4.x + k4.y*k4.y + k4.z*k4.z + k4.w*k4.w;
    #pragma unroll
    for (int d = 16; d >= 1; d >>= 1) {
        sq += __shfl_xor_sync(0xffffffffu, sq, d);
        sk += __shfl_xor_sync(0xffffffffu, sk, d);
    }
    const float qscale = rsqrtf(sq + 1e-6f) * 0.08838834764831845f; // * DK^-0.5
    const float kscale = rsqrtf(sk + 1e-6f);
    float* qo = qn + (size_t)warp * DK + lane * 4;
    float* ko = kn + (size_t)warp * DK + lane * 4;
    *(float4*)qo = make_float4(q4.x*qscale, q4.y*qscale, q4.z*qscale, q4.w*qscale);
    *(float4*)ko = make_float4(k4.x*kscale, k4.y*kscale, k4.z*kscale, k4.w*kscale);
}

// ---------------- beta = sigmoid(b); g = -exp(A_log)*softplus(a + dt_bias) ----------------
__global__ void __launch_bounds__(256) betag(
    const float* __restrict__ bb, const float* __restrict__ aa,
    const float* __restrict__ A_log, const float* __restrict__ dt_bias,
    float* __restrict__ beta, float* __restrict__ g)
{
    const int i = blockIdx.x * 256 + threadIdx.x; // < MROWS*HV
    const int h = i & (HV - 1);
    float bv = bb[i];
    float av = aa[i] + dt_bias[h];
    beta[i] = 1.f / (1.f + expf(-bv));
    float sp = (av > 20.f) ? av : log1pf(expf(av));
    g[i] = -expf(A_log[h]) * sp;
}

// ---------------- gated delta-rule recurrence ----------------
// grid: B*HV*2 = 128 CTAs (each handles 64 of the 128 V-columns of one (b,h) state)
// block: 128 threads; thread owns a 64-row half-column of S in registers.
// warp w covers 16 columns x 2 halves; partner halves via shfl.xor 16.
__global__ void __launch_bounds__(128) recurrence(
    const float* __restrict__ qn, const float* __restrict__ kn,
    const float* __restrict__ conv, const float* __restrict__ gg,
    const float* __restrict__ bbeta, float* __restrict__ core)
{
    const int blk = blockIdx.x;
    const int b  = blk >> 6;
    const int h  = (blk >> 1) & 31;
    const int vh = blk & 1;
    const int kh = h >> 1;                     // repeat_interleave(2) head map
    const int tid = threadIdx.x;
    const int w = tid >> 5, lane = tid & 31;
    const int half = lane >> 4;
    const int col  = vh * 64 + w * 16 + (lane & 15);
    const int row0 = half * 64;

    __shared__ __align__(16) float qs[2][128];
    __shared__ __align__(16) float ks[2][128];

    float S[64];
    #pragma unroll
    for (int i = 0; i < 64; i++) S[i] = 0.f;

    const float* qptr = qn + ((size_t)b * LL * HK + kh) * DK + tid;
    const float* kptr = kn + ((size_t)b * LL * HK + kh) * DK + tid;
    const float* vptr = conv + (size_t)b * LL * CONV_DIM + 2 * KEY_DIM + h * DV + col;
    const float* gptr = gg    + (size_t)b * LL * HV + h;
    const float* bptr = bbeta + (size_t)b * LL * HV + h;
    float* optr = core + ((size_t)b * LL * HV + h) * DV + col;

    // stage step 0
    float qN = qptr[0], kN = kptr[0];
    float vc = vptr[0], gc = gptr[0], bc = bptr[0];
    qs[0][tid] = qN; ks[0][tid] = kN;
    __syncthreads();

    for (int l = 0; l < LL; l++) {
        const int cur = l & 1, nxt = cur ^ 1;
        // prefetch next step (overlaps with compute)
        float vN = vc, gN = gc, bN = bc;
        if (l + 1 < LL) {
            size_t o = (size_t)(l + 1);
            qN = qptr[o * (HK * DK)];
            kN = kptr[o * (HK * DK)];
            vN = vptr[o * CONV_DIM];
            gN = gptr[o * HV];
            bN = bptr[o * HV];
        }

        const float eg = __expf(gc);
        const float* kcur = &ks[cur][row0];
        const float* qcur = &qs[cur][row0];

        // pass 1: kv = k . S_old   (then decay by eg)
        float a0 = 0.f, a1 = 0.f, a2 = 0.f, a3 = 0.f;
        #pragma unroll
        for (int i = 0; i < 16; i++) {
            float4 k4 = *(const float4*)(kcur + 4 * i);
            a0 = fmaf(k4.x, S[4*i+0], a0);
            a1 = fmaf(k4.y, S[4*i+1], a1);
            a2 = fmaf(k4.z, S[4*i+2], a2);
            a3 = fmaf(k4.w, S[4*i+3], a3);
        }
        float kv = (a0 + a1) + (a2 + a3);
        kv += __shfl_xor_sync(0xffffffffu, kv, 16);
        const float delta = (vc - eg * kv) * bc;

        // pass 2: S = eg*S + k*delta ; o = q . S
        float o0 = 0.f, o1 = 0.f, o2 = 0.f, o3 = 0.f;
        #pragma unroll
        for (int i = 0; i < 16; i++) {
            float4 k4 = *(const float4*)(kcur + 4 * i);
            float4 q4 = *(const float4*)(qcur + 4 * i);
            S[4*i+0] = fmaf(eg, S[4*i+0], k4.x * delta);
            S[4*i+1] = fmaf(eg, S[4*i+1], k4.y * delta);
            S[4*i+2] = fmaf(eg, S[4*i+2], k4.z * delta);
            S[4*i+3] = fmaf(eg, S[4*i+3], k4.w * delta);
            o0 = fmaf(q4.x, S[4*i+0], o0);
            o1 = fmaf(q4.y, S[4*i+1], o1);
            o2 = fmaf(q4.z, S[4*i+2], o2);
            o3 = fmaf(q4.w, S[4*i+3], o3);
        }
        float o = (o0 + o1) + (o2 + o3);
        o += __shfl_xor_sync(0xffffffffu, o, 16);
        if (half == 0) optr[(size_t)l * VAL_DIM] = o;

        // publish prefetched q/k for next step
        qs[nxt][tid] = qN; ks[nxt][tid] = kN;
        vc = vN; gc = gN; bc = bN;
        __syncthreads();
    }
}

// ---------------- gated RMSNorm: core = rmsnorm(core * silu(z)) * norm_w ----------------
__global__ void __launch_bounds__(256) gated_rmsnorm(
    float* __restrict__ core, const float* __restrict__ z, const float* __restrict__ nw)
{
    const int warp = (blockIdx.x * 256 + threadIdx.x) >> 5;  // row over MROWS*HV
    const int lane = threadIdx.x & 31;
    const size_t base = (size_t)warp * DV + lane * 4;

    float4 c4 = *(const float4*)(core + base);
    float4 z4 = *(const float4*)(z + base);
    float gx = c4.x * (z4.x / (1.f + expf(-z4.x)));
    float gy = c4.y * (z4.y / (1.f + expf(-z4.y)));
    float gz = c4.z * (z4.z / (1.f + expf(-z4.z)));
    float gw = c4.w * (z4.w / (1.f + expf(-z4.w)));
    float ss = gx*gx + gy*gy + gz*gz + gw*gw;
    #pragma unroll
    for (int d = 16; d >= 1; d >>= 1) ss += __shfl_xor_sync(0xffffffffu, ss, d);
    const float scale = rsqrtf(ss * (1.f / DV) + 1e-6f);
    float4 w4 = *(const float4*)(nw + lane * 4);
    *(float4*)(core + base) =
        make_float4(gx * scale * w4.x, gy * scale * w4.y, gz * scale * w4.z, gw * scale * w4.w);
}

// ---------------- launch ----------------
extern "C" void kernel_launch(void* const* d_in, const int* in_sizes, int n_in,
                              void* d_out, int out_size)
{
    const float* H       = (const float*)d_in[0];
    const float* W_qkv   = (const float*)d_in[1];
    const float* W_z     = (const float*)d_in[2];
    const float* W_b     = (const float*)d_in[3];
    const float* W_a     = (const float*)d_in[4];
    const float* conv_w  = (const float*)d_in[5];
    const float* dt_bias = (const float*)d_in[6];
    const float* A_log   = (const float*)d_in[7];
    const float* norm_w  = (const float*)d_in[8];
    const float* W_out   = (const float*)d_in[9];
    float* out = (float*)d_out;

    float *mixed, *convb, *z, *core, *qn, *kn, *bb, *aa, *beta, *g;
    cudaGetSymbolAddress((void**)&mixed, g_mixed);
    cudaGetSymbolAddress((void**)&convb, g_conv);
    cudaGetSymbolAddress((void**)&z,     g_z);
    cudaGetSymbolAddress((void**)&core,  g_core);
    cudaGetSymbolAddress((void**)&qn,    g_qn);
    cudaGetSymbolAddress((void**)&kn,    g_kn);
    cudaGetSymbolAddress((void**)&bb,    g_bv);
    cudaGetSymbolAddress((void**)&aa,    g_av);
    cudaGetSymbolAddress((void**)&beta,  g_beta);
    cudaGetSymbolAddress((void**)&g,     g_g);

    // 1) big projections
    sgemm128<<<dim3(CONV_DIM / 128, MROWS / 128), 256>>>(H, W_qkv, mixed, MROWS, CONV_DIM, DD);
    sgemm128<<<dim3(VAL_DIM / 128, MROWS / 128), 256>>>(H, W_z, z, MROWS, VAL_DIM, DD);
    gemm_ba<<<MROWS / 8, 64>>>(H, W_b, W_a, bb, aa);

    // 2) conv + activation + norms
    conv_silu<<<(MROWS * (size_t)CONV_DIM) / 256, 256>>>(mixed, conv_w, convb);
    qk_norm<<<(MROWS * HK) / 8, 256>>>(convb, qn, kn);
    betag<<<(MROWS * HV) / 256, 256>>>(bb, aa, A_log, dt_bias, beta, g);

    // 3) sequential gated delta-rule scan
    recurrence<<<BB * HV * 2, 128>>>(qn, kn, convb, g, beta, core);

    // 4) gated RMSNorm + output projection
    gated_rmsnorm<<<(MROWS * HV) / 8, 256>>>(core, z, norm_w);
    sgemm128<<<dim3(DD / 128, MROWS / 128), 256>>>(core, W_out, out, MROWS, DD, VAL_DIM);
}

// round 8
// speedup vs baseline: 1.9529x; 1.9529x over previous
#include <cuda_runtime.h>
#include <cuda_bf16.h>
#include <cstdint>
#include <cstdio>

// ---------------- problem constants ----------------
#define BB   2
#define LL   2048
#define DD   2048
#define HV   32
#define HK   16
#define DK   128
#define DV   128
#define KCONV 4
#define KEY_DIM  2048
#define VAL_DIM  4096
#define CONV_DIM 8192
#define MROWS (BB*LL)          // 4096

// ---------------- scratch (static device globals; no runtime alloc) ----------------
__device__ float g_mixed[(size_t)MROWS * CONV_DIM];   // qkv mix (fp32)
__device__ float g_conv [(size_t)MROWS * CONV_DIM];   // post conv+silu
__device__ float g_z    [(size_t)MROWS * VAL_DIM];    // gate
__device__ float g_core [(size_t)MROWS * VAL_DIM];    // scan output (fp32)
__device__ float g_qn   [(size_t)MROWS * HK * DK];
__device__ float g_kn   [(size_t)MROWS * HK * DK];
__device__ float g_bv   [(size_t)MROWS * HV];
__device__ float g_av   [(size_t)MROWS * HV];
__device__ float g_beta [(size_t)MROWS * HV];
__device__ float g_g    [(size_t)MROWS * HV];

// bf16 split operands
__device__ __nv_bfloat16 g_Hhi[(size_t)MROWS * DD];
__device__ __nv_bfloat16 g_Hlo[(size_t)MROWS * DD];
__device__ __nv_bfloat16 g_Wqkvt_hi[(size_t)CONV_DIM * DD];   // [N,K] = [8192,2048]
__device__ __nv_bfloat16 g_Wqkvt_lo[(size_t)CONV_DIM * DD];
__device__ __nv_bfloat16 g_Wzt_hi[(size_t)VAL_DIM * DD];      // [4096,2048]
__device__ __nv_bfloat16 g_Wzt_lo[(size_t)VAL_DIM * DD];
__device__ __nv_bfloat16 g_Woutt_hi[(size_t)DD * VAL_DIM];    // [2048,4096]
__device__ __nv_bfloat16 g_Woutt_lo[(size_t)DD * VAL_DIM];
__device__ __nv_bfloat16 g_chi[(size_t)MROWS * VAL_DIM];      // gated core hi
__device__ __nv_bfloat16 g_clo[(size_t)MROWS * VAL_DIM];      // gated core lo

// ================= PTX helpers (sm_103 baseline ISA only; NO 'a'-gated ops) =================
__device__ __forceinline__ uint32_t s2u(const void* p) {
    uint32_t a;
    asm("{ .reg .u64 t; cvta.to.shared.u64 t, %1; cvt.u32.u64 %0, t; }" : "=r"(a) : "l"(p));
    return a;
}
__device__ __forceinline__ void cp16(uint32_t s, const void* g) {
    asm volatile("cp.async.cg.shared.global [%0], [%1], 16;" :: "r"(s), "l"(g));
}
#define CP_COMMIT() asm volatile("cp.async.commit_group;" ::: "memory")
#define CP_WAIT(n)  asm volatile("cp.async.wait_group %0;" :: "n"(n) : "memory")

#define LDSM4(r, a) \
    asm volatile("ldmatrix.sync.aligned.m8n8.x4.shared.b16 {%0,%1,%2,%3}, [%4];" \
                 : "=r"((r)[0]), "=r"((r)[1]), "=r"((r)[2]), "=r"((r)[3]) : "r"(a))
#define LDSM2(r, a) \
    asm volatile("ldmatrix.sync.aligned.m8n8.x2.shared.b16 {%0,%1}, [%2];" \
                 : "=r"((r)[0]), "=r"((r)[1]) : "r"(a))
#define MMA16816(d, a, b) \
    asm volatile("mma.sync.aligned.m16n8k16.row.col.f32.bf16.bf16.f32 " \
                 "{%0,%1,%2,%3},{%4,%5,%6,%7},{%8,%9},{%0,%1,%2,%3};" \
                 : "+f"((d)[0]), "+f"((d)[1]), "+f"((d)[2]), "+f"((d)[3]) \
                 : "r"((a)[0]), "r"((a)[1]), "r"((a)[2]), "r"((a)[3]), \
                   "r"((b)[0]), "r"((b)[1]))

// ================= split-bf16 HMMA GEMM =================
// C[M,N] = (Ahi+Alo)[M,K] . (Bhi+Blo)[N,K]^T  (drops lo.lo term)
// 128x128 tile, 8 warps (2x4), K-stage 32, double-buffered cp.async.
// Smem per stage: Ahi/Alo/Bhi/Blo, each 128 rows x 64B, chunk-XOR swizzled.
#define GSTAGE 32768   // 4 * 8192 bytes
#define GSMEM  (2 * GSTAGE)

__global__ void __launch_bounds__(256, 1) gemm_hmma_split(
    const __nv_bfloat16* __restrict__ Ah, const __nv_bfloat16* __restrict__ Al,
    const __nv_bfloat16* __restrict__ Bh, const __nv_bfloat16* __restrict__ Bl,
    float* __restrict__ C, int M, int N, int K)
{
    extern __shared__ __align__(16) char smraw[];
    const uint32_t sbase = s2u(smraw);
    const int tid = threadIdx.x;
    const int wid = tid >> 5, lane = tid & 31;
    const int bm = blockIdx.y * 128;
    const int bn = blockIdx.x * 128;
    const int wm = (wid & 1) * 64;   // warp row offset within tile
    const int wn = (wid >> 1) * 32;  // warp col offset within tile

    // swizzled smem byte offset for (row, 16B-chunk c in 0..3)
    auto swoff = [](int row, int c) -> uint32_t {
        return (uint32_t)(row * 64 + ((c ^ ((row >> 1) & 3)) << 4));
    };

    const int S = K / 32;

    auto load_stage = [&](int s) {
        const uint32_t sb = sbase + (uint32_t)(s & 1) * GSTAGE;
        const int k0 = s * 32;
        #pragma unroll
        for (int i = 0; i < 2; i++) {
            int idx = tid + 256 * i;       // 0..511
            int row = idx >> 2;
            int c   = idx & 3;
            uint32_t off = swoff(row, c);
            size_t ga = (size_t)(bm + row) * K + k0 + c * 8;
            size_t gb = (size_t)(bn + row) * K + k0 + c * 8;
            cp16(sb + off,          Ah + ga);
            cp16(sb + 8192 + off,   Al + ga);
            cp16(sb + 16384 + off,  Bh + gb);
            cp16(sb + 24576 + off,  Bl + gb);
        }
        CP_COMMIT();
    };

    float acc[4][4][4];
    #pragma unroll
    for (int mi = 0; mi < 4; mi++)
        #pragma unroll
        for (int ni = 0; ni < 4; ni++)
            #pragma unroll
            for (int r = 0; r < 4; r++) acc[mi][ni][r] = 0.f;

    load_stage(0);

    for (int s = 0; s < S; s++) {
        if (s + 1 < S) { load_stage(s + 1); CP_WAIT(1); }
        else           { CP_WAIT(0); }
        __syncthreads();

        const uint32_t sb = sbase + (uint32_t)(s & 1) * GSTAGE;

        #pragma unroll
        for (int kk = 0; kk < 2; kk++) {
            uint32_t ah[4][4], alo[4][4], bh[4][2], bl[4][2];
            #pragma unroll
            for (int mi = 0; mi < 4; mi++) {
                int row = wm + mi * 16 + (lane & 15);
                int c   = (kk << 1) | (lane >> 4);
                uint32_t addr = sb + swoff(row, c);
                LDSM4(ah[mi],  addr);
                LDSM4(alo[mi], addr + 8192);
            }
            #pragma unroll
            for (int ni = 0; ni < 4; ni++) {
                int row = wn + ni * 8 + (lane & 7);
                int c   = (kk << 1) | ((lane >> 3) & 1);
                uint32_t addr = sb + 16384 + swoff(row, c);
                LDSM2(bh[ni], addr);
                LDSM2(bl[ni], addr + 8192);
            }
            #pragma unroll
            for (int mi = 0; mi < 4; mi++)
                #pragma unroll
                for (int ni = 0; ni < 4; ni++) {
                    MMA16816(acc[mi][ni], ah[mi],  bh[ni]);
                    MMA16816(acc[mi][ni], ah[mi],  bl[ni]);
                    MMA16816(acc[mi][ni], alo[mi], bh[ni]);
                }
        }
        __syncthreads();
    }

    // epilogue: c0,c1 -> (row, col..col+1); c2,c3 -> (row+8, col..col+1)
    #pragma unroll
    for (int mi = 0; mi < 4; mi++) {
        #pragma unroll
        for (int ni = 0; ni < 4; ni++) {
            int row = bm + wm + mi * 16 + (lane >> 2);
            int col = bn + wn + ni * 8 + (lane & 3) * 2;
            float* p = C + (size_t)row * N + col;
            *(float2*)p = make_float2(acc[mi][ni][0], acc[mi][ni][1]);
            *(float2*)(p + (size_t)8 * N) = make_float2(acc[mi][ni][2], acc[mi][ni][3]);
        }
    }
}

// ================= operand prep =================
__global__ void __launch_bounds__(256) split_bf16(
    const float4* __restrict__ x, __nv_bfloat16* __restrict__ hi,
    __nv_bfloat16* __restrict__ lo, int n4)
{
    int i = blockIdx.x * 256 + threadIdx.x;
    if (i >= n4) return;
    float4 v = x[i];
    __nv_bfloat16 h0 = __float2bfloat16(v.x), h1 = __float2bfloat16(v.y);
    __nv_bfloat16 h2 = __float2bfloat16(v.z), h3 = __float2bfloat16(v.w);
    __nv_bfloat162* H = (__nv_bfloat162*)(hi) + 2 * (size_t)i;
    __nv_bfloat162* L = (__nv_bfloat162*)(lo) + 2 * (size_t)i;
    H[0] = __nv_bfloat162(h0, h1);
    H[1] = __nv_bfloat162(h2, h3);
    L[0] = __nv_bfloat162(__float2bfloat16(v.x - __bfloat162float(h0)),
                          __float2bfloat16(v.y - __bfloat162float(h1)));
    L[1] = __nv_bfloat162(__float2bfloat16(v.z - __bfloat162float(h2)),
                          __float2bfloat16(v.w - __bfloat162float(h3)));
}

// transpose W[R,C] fp32 -> out[C,R] bf16 hi/lo
__global__ void __launch_bounds__(256) transpose_split(
    const float* __restrict__ W, __nv_bfloat16* __restrict__ hi,
    __nv_bfloat16* __restrict__ lo, int R, int C)
{
    __shared__ float t[32][33];
    const int c0 = blockIdx.x * 32, r0 = blockIdx.y * 32;
    const int tx = threadIdx.x & 31;
    const int ty0 = threadIdx.x >> 5;
    #pragma unroll
    for (int i = 0; i < 32; i += 8)
        t[ty0 + i][tx] = W[(size_t)(r0 + ty0 + i) * C + c0 + tx];
    __syncthreads();
    #pragma unroll
    for (int i = 0; i < 32; i += 8) {
        float v = t[tx][ty0 + i];
        __nv_bfloat16 h = __float2bfloat16(v);
        size_t o = (size_t)(c0 + ty0 + i) * R + r0 + tx;
        hi[o] = h;
        lo[o] = __float2bfloat16(v - __bfloat162float(h));
    }
}

// ---------------- skinny GEMM: b = H@W_b, a = H@W_a ----------------
__global__ void __launch_bounds__(64) gemm_ba(
    const float* __restrict__ H, const float* __restrict__ Wb,
    const float* __restrict__ Wa, float* __restrict__ ob, float* __restrict__ oa)
{
    const int m0 = blockIdx.x * 8;
    const int t  = threadIdx.x;
    const float* W = (t < 32) ? Wb : Wa;
    const int colw = t & 31;
    float s[8];
    #pragma unroll
    for (int r = 0; r < 8; r++) s[r] = 0.f;
    for (int k = 0; k < DD; k++) {
        float wv = W[(size_t)k * 32 + colw];
        #pragma unroll
        for (int r = 0; r < 8; r++)
            s[r] = fmaf(H[(size_t)(m0 + r) * DD + k], wv, s[r]);
    }
    #pragma unroll
    for (int r = 0; r < 8; r++) {
        if (t < 32) ob[(size_t)(m0 + r) * 32 + colw] = s[r];
        else        oa[(size_t)(m0 + r) * 32 + colw] = s[r];
    }
}

// ---------------- causal depthwise conv (K=4) + SiLU, float4 ----------------
__global__ void __launch_bounds__(256) conv_silu4(
    const float4* __restrict__ x, const float4* __restrict__ w, float4* __restrict__ y)
{
    const size_t i = (size_t)blockIdx.x * 256 + threadIdx.x;  // float4 idx < MROWS*2048
    const int c4 = (int)(i & 2047);
    const int l  = (int)((i >> 11) & (LL - 1));
    const float4 zero = make_float4(0.f, 0.f, 0.f, 0.f);
    float4 x0 = x[i];
    float4 x1 = (l >= 1) ? x[i - 2048] : zero;
    float4 x2 = (l >= 2) ? x[i - 4096] : zero;
    float4 x3 = (l >= 3) ? x[i - 6144] : zero;
    float4 w0 = w[4 * c4 + 0], w1 = w[4 * c4 + 1], w2 = w[4 * c4 + 2], w3 = w[4 * c4 + 3];
    float4 a;
    a.x = fmaf(w0.x, x3.x, fmaf(w0.y, x2.x, fmaf(w0.z, x1.x, w0.w * x0.x)));
    a.y = fmaf(w1.x, x3.y, fmaf(w1.y, x2.y, fmaf(w1.z, x1.y, w1.w * x0.y)));
    a.z = fmaf(w2.x, x3.z, fmaf(w2.y, x2.z, fmaf(w2.z, x1.z, w2.w * x0.z)));
    a.w = fmaf(w3.x, x3.w, fmaf(w3.y, x2.w, fmaf(w3.z, x1.w, w3.w * x0.w)));
    a.x = a.x / (1.f + __expf(-a.x));
    a.y = a.y / (1.f + __expf(-a.y));
    a.z = a.z / (1.f + __expf(-a.z));
    a.w = a.w / (1.f + __expf(-a.w));
    y[i] = a;
}

// ---------------- q/k l2norm (+ q scale) ----------------
__global__ void __launch_bounds__(256) qk_norm(
    const float* __restrict__ conv, float* __restrict__ qn, float* __restrict__ kn)
{
    const int warp = (blockIdx.x * 256 + threadIdx.x) >> 5;
    const int lane = threadIdx.x & 31;
    const int bl = warp >> 4;
    const int kh = warp & 15;
    const float* qp = conv + (size_t)bl * CONV_DIM + kh * DK + lane * 4;
    const float* kp = qp + KEY_DIM;
    float4 q4 = *(const float4*)qp;
    float4 k4 = *(const float4*)kp;
    float sq = q4.x*q4.x + q4.y*q4.y + q4.z*q4.z + q4.w*q4.w;
    float sk = k4.x*k4.x + k4.y*k4.y + k4.z*k4.z + k4.w*k4.w;
    #pragma unroll
    for (int d = 16; d >= 1; d >>= 1) {
        sq += __shfl_xor_sync(0xffffffffu, sq, d);
        sk += __shfl_xor_sync(0xffffffffu, sk, d);
    }
    const float qscale = rsqrtf(sq + 1e-6f) * 0.08838834764831845f;
    const float kscale = rsqrtf(sk + 1e-6f);
    float* qo = qn + (size_t)warp * DK + lane * 4;
    float* ko = kn + (size_t)warp * DK + lane * 4;
    *(float4*)qo = make_float4(q4.x*qscale, q4.y*qscale, q4.z*qscale, q4.w*qscale);
    *(float4*)ko = make_float4(k4.x*kscale, k4.y*kscale, k4.z*kscale, k4.w*kscale);
}

// ---------------- beta/g ----------------
__global__ void __launch_bounds__(256) betag(
    const float* __restrict__ bb, const float* __restrict__ aa,
    const float* __restrict__ A_log, const float* __restrict__ dt_bias,
    float* __restrict__ beta, float* __restrict__ g)
{
    const int i = blockIdx.x * 256 + threadIdx.x;
    const int h = i & (HV - 1);
    float bv = bb[i];
    float av = aa[i] + dt_bias[h];
    beta[i] = 1.f / (1.f + expf(-bv));
    float sp = (av > 20.f) ? av : log1pf(expf(av));
    g[i] = -expf(A_log[h]) * sp;
}

// ---------------- gated delta-rule recurrence ----------------
__global__ void __launch_bounds__(128) recurrence(
    const float* __restrict__ qn, const float* __restrict__ kn,
    const float* __restrict__ conv, const float* __restrict__ gg,
    const float* __restrict__ bbeta, float* __restrict__ core)
{
    const int blk = blockIdx.x;
    const int b  = blk >> 6;
    const int h  = (blk >> 1) & 31;
    const int vh = blk & 1;
    const int kh = h >> 1;
    const int tid = threadIdx.x;
    const int w = tid >> 5, lane = tid & 31;
    const int half = lane >> 4;
    const int col  = vh * 64 + w * 16 + (lane & 15);
    const int row0 = half * 64;

    __shared__ __align__(16) float qs[2][128];
    __shared__ __align__(16) float ks[2][128];

    float S[64];
    #pragma unroll
    for (int i = 0; i < 64; i++) S[i] = 0.f;

    const float* qptr = qn + ((size_t)b * LL * HK + kh) * DK + tid;
    const float* kptr = kn + ((size_t)b * LL * HK + kh) * DK + tid;
    const float* vptr = conv + (size_t)b * LL * CONV_DIM + 2 * KEY_DIM + h * DV + col;
    const float* gptr = gg    + (size_t)b * LL * HV + h;
    const float* bptr = bbeta + (size_t)b * LL * HV + h;
    float* optr = core + ((size_t)b * LL * HV + h) * DV + col;

    float qN = qptr[0], kN = kptr[0];
    float vc = vptr[0], gc = gptr[0], bc = bptr[0];
    qs[0][tid] = qN; ks[0][tid] = kN;
    __syncthreads();

    for (int l = 0; l < LL; l++) {
        const int cur = l & 1, nxt = cur ^ 1;
        float vN = vc, gN = gc, bN = bc;
        if (l + 1 < LL) {
            size_t o = (size_t)(l + 1);
            qN = qptr[o * (HK * DK)];
            kN = kptr[o * (HK * DK)];
            vN = vptr[o * CONV_DIM];
            gN = gptr[o * HV];
            bN = bptr[o * HV];
        }

        const float eg = __expf(gc);
        const float* kcur = &ks[cur][row0];
        const float* qcur = &qs[cur][row0];

        float a0 = 0.f, a1 = 0.f, a2 = 0.f, a3 = 0.f;
        #pragma unroll
        for (int i = 0; i < 16; i++) {
            float4 k4 = *(const float4*)(kcur + 4 * i);
            a0 = fmaf(k4.x, S[4*i+0], a0);
            a1 = fmaf(k4.y, S[4*i+1], a1);
            a2 = fmaf(k4.z, S[4*i+2], a2);
            a3 = fmaf(k4.w, S[4*i+3], a3);
        }
        float kv = (a0 + a1) + (a2 + a3);
        kv += __shfl_xor_sync(0xffffffffu, kv, 16);
        const float delta = (vc - eg * kv) * bc;

        float o0 = 0.f, o1 = 0.f, o2 = 0.f, o3 = 0.f;
        #pragma unroll
        for (int i = 0; i < 16; i++) {
            float4 k4 = *(const float4*)(kcur + 4 * i);
            float4 q4 = *(const float4*)(qcur + 4 * i);
            S[4*i+0] = fmaf(eg, S[4*i+0], k4.x * delta);
            S[4*i+1] = fmaf(eg, S[4*i+1], k4.y * delta);
            S[4*i+2] = fmaf(eg, S[4*i+2], k4.z * delta);
            S[4*i+3] = fmaf(eg, S[4*i+3], k4.w * delta);
            o0 = fmaf(q4.x, S[4*i+0], o0);
            o1 = fmaf(q4.y, S[4*i+1], o1);
            o2 = fmaf(q4.z, S[4*i+2], o2);
            o3 = fmaf(q4.w, S[4*i+3], o3);
        }
        float o = (o0 + o1) + (o2 + o3);
        o += __shfl_xor_sync(0xffffffffu, o, 16);
        if (half == 0) optr[(size_t)l * VAL_DIM] = o;

        qs[nxt][tid] = qN; ks[nxt][tid] = kN;
        vc = vN; gc = gN; bc = bN;
        __syncthreads();
    }
}

// ---------------- gated RMSNorm -> bf16 hi/lo ----------------
__global__ void __launch_bounds__(256) gated_rmsnorm_split(
    const float* __restrict__ core, const float* __restrict__ z,
    const float* __restrict__ nw,
    __nv_bfloat16* __restrict__ chi, __nv_bfloat16* __restrict__ clo)
{
    const int warp = (blockIdx.x * 256 + threadIdx.x) >> 5;
    const int lane = threadIdx.x & 31;
    const size_t base = (size_t)warp * DV + lane * 4;

    float4 c4 = *(const float4*)(core + base);
    float4 z4 = *(const float4*)(z + base);
    float gx = c4.x * (z4.x / (1.f + expf(-z4.x)));
    float gy = c4.y * (z4.y / (1.f + expf(-z4.y)));
    float gz = c4.z * (z4.z / (1.f + expf(-z4.z)));
    float gw = c4.w * (z4.w / (1.f + expf(-z4.w)));
    float ss = gx*gx + gy*gy + gz*gz + gw*gw;
    #pragma unroll
    for (int d = 16; d >= 1; d >>= 1) ss += __shfl_xor_sync(0xffffffffu, ss, d);
    const float scale = rsqrtf(ss * (1.f / DV) + 1e-6f);
    float4 w4 = *(const float4*)(nw + lane * 4);
    float v0 = gx * scale * w4.x, v1 = gy * scale * w4.y;
    float v2 = gz * scale * w4.z, v3 = gw * scale * w4.w;

    __nv_bfloat16 h0 = __float2bfloat16(v0), h1 = __float2bfloat16(v1);
    __nv_bfloat16 h2 = __float2bfloat16(v2), h3 = __float2bfloat16(v3);
    __nv_bfloat162* H = (__nv_bfloat162*)(chi + base);
    __nv_bfloat162* L = (__nv_bfloat162*)(clo + base);
    H[0] = __nv_bfloat162(h0, h1);
    H[1] = __nv_bfloat162(h2, h3);
    L[0] = __nv_bfloat162(__float2bfloat16(v0 - __bfloat162float(h0)),
                          __float2bfloat16(v1 - __bfloat162float(h1)));
    L[1] = __nv_bfloat162(__float2bfloat16(v2 - __bfloat162float(h2)),
                          __float2bfloat16(v3 - __bfloat162float(h3)));
}

// ---------------- launch ----------------
extern "C" void kernel_launch(void* const* d_in, const int* in_sizes, int n_in,
                              void* d_out, int out_size)
{
    const float* H       = (const float*)d_in[0];
    const float* W_qkv   = (const float*)d_in[1];
    const float* W_z     = (const float*)d_in[2];
    const float* W_b     = (const float*)d_in[3];
    const float* W_a     = (const float*)d_in[4];
    const float* conv_w  = (const float*)d_in[5];
    const float* dt_bias = (const float*)d_in[6];
    const float* A_log   = (const float*)d_in[7];
    const float* norm_w  = (const float*)d_in[8];
    const float* W_out   = (const float*)d_in[9];
    float* out = (float*)d_out;

    float *mixed, *convb, *z, *core, *qn, *kn, *bb, *aa, *beta, *g;
    cudaGetSymbolAddress((void**)&mixed, g_mixed);
    cudaGetSymbolAddress((void**)&convb, g_conv);
    cudaGetSymbolAddress((void**)&z,     g_z);
    cudaGetSymbolAddress((void**)&core,  g_core);
    cudaGetSymbolAddress((void**)&qn,    g_qn);
    cudaGetSymbolAddress((void**)&kn,    g_kn);
    cudaGetSymbolAddress((void**)&bb,    g_bv);
    cudaGetSymbolAddress((void**)&aa,    g_av);
    cudaGetSymbolAddress((void**)&beta,  g_beta);
    cudaGetSymbolAddress((void**)&g,     g_g);

    __nv_bfloat16 *Hhi, *Hlo, *Wqh, *Wql, *Wzh, *Wzl, *Woh, *Wol, *chi, *clo;
    cudaGetSymbolAddress((void**)&Hhi, g_Hhi);
    cudaGetSymbolAddress((void**)&Hlo, g_Hlo);
    cudaGetSymbolAddress((void**)&Wqh, g_Wqkvt_hi);
    cudaGetSymbolAddress((void**)&Wql, g_Wqkvt_lo);
    cudaGetSymbolAddress((void**)&Wzh, g_Wzt_hi);
    cudaGetSymbolAddress((void**)&Wzl, g_Wzt_lo);
    cudaGetSymbolAddress((void**)&Woh, g_Woutt_hi);
    cudaGetSymbolAddress((void**)&Wol, g_Woutt_lo);
    cudaGetSymbolAddress((void**)&chi, g_chi);
    cudaGetSymbolAddress((void**)&clo, g_clo);

    cudaFuncSetAttribute(gemm_hmma_split, cudaFuncAttributeMaxDynamicSharedMemorySize, GSMEM);

    // 0) operand prep: split H, transpose+split weights
    split_bf16<<<(MROWS * DD / 4) / 256, 256>>>((const float4*)H, Hhi, Hlo, MROWS * DD / 4);
    transpose_split<<<dim3(CONV_DIM / 32, DD / 32), 256>>>(W_qkv, Wqh, Wql, DD, CONV_DIM);
    transpose_split<<<dim3(VAL_DIM / 32, DD / 32), 256>>>(W_z, Wzh, Wzl, DD, VAL_DIM);
    transpose_split<<<dim3(DD / 32, VAL_DIM / 32), 256>>>(W_out, Woh, Wol, VAL_DIM, DD);

    // 1) big projections (HMMA bf16 split)
    gemm_hmma_split<<<dim3(CONV_DIM / 128, MROWS / 128), 256, GSMEM>>>(
        Hhi, Hlo, Wqh, Wql, mixed, MROWS, CONV_DIM, DD);
    gemm_hmma_split<<<dim3(VAL_DIM / 128, MROWS / 128), 256, GSMEM>>>(
        Hhi, Hlo, Wzh, Wzl, z, MROWS, VAL_DIM, DD);
    gemm_ba<<<MROWS / 8, 64>>>(H, W_b, W_a, bb, aa);

    // 2) conv + activation + norms
    conv_silu4<<<(MROWS * (size_t)CONV_DIM / 4) / 256, 256>>>(
        (const float4*)mixed, (const float4*)conv_w, (float4*)convb);
    qk_norm<<<(MROWS * HK) / 8, 256>>>(convb, qn, kn);
    betag<<<(MROWS * HV) / 256, 256>>>(bb, aa, A_log, dt_bias, beta, g);

    // 3) sequential gated delta-rule scan
    recurrence<<<BB * HV * 2, 128>>>(qn, kn, convb, g, beta, core);

    // 4) gated RMSNorm (-> bf16 hi/lo) + output projection (HMMA bf16 split)
    gated_rmsnorm_split<<<(MROWS * HV) / 8, 256>>>(core, z, norm_w, chi, clo);
    gemm_hmma_split<<<dim3(DD / 128, MROWS / 128), 256, GSMEM>>>(
        chi, clo, Woh, Wol, out, MROWS, DD, VAL_DIM);
}

// round 10
// speedup vs baseline: 2.0066x; 1.0275x over previous
#include <cuda_runtime.h>
#include <cuda_bf16.h>
#include <cstdint>
#include <cstdio>

// ---------------- problem constants ----------------
#define BB   2
#define LL   2048
#define DD   2048
#define HV   32
#define HK   16
#define DK   128
#define DV   128
#define KCONV 4
#define KEY_DIM  2048
#define VAL_DIM  4096
#define CONV_DIM 8192
#define MROWS (BB*LL)          // 4096

// ---------------- scratch (static device globals; no runtime alloc) ----------------
__device__ float g_mixed[(size_t)MROWS * CONV_DIM];   // qkv mix (fp32)
__device__ float g_conv [(size_t)MROWS * CONV_DIM];   // post conv+silu
__device__ float g_z    [(size_t)MROWS * VAL_DIM];    // gate
__device__ float g_core [(size_t)MROWS * VAL_DIM];    // scan output (fp32)
__device__ float g_qn   [(size_t)MROWS * HK * DK];
__device__ float g_kn   [(size_t)MROWS * HK * DK];
__device__ float g_bv   [(size_t)MROWS * HV];
__device__ float g_av   [(size_t)MROWS * HV];
__device__ float g_beta [(size_t)MROWS * HV];
__device__ float g_g    [(size_t)MROWS * HV];

// bf16 split operands
__device__ __nv_bfloat16 g_Hhi[(size_t)MROWS * DD];
__device__ __nv_bfloat16 g_Hlo[(size_t)MROWS * DD];
__device__ __nv_bfloat16 g_Wqkvt_hi[(size_t)CONV_DIM * DD];   // [N,K] = [8192,2048]
__device__ __nv_bfloat16 g_Wqkvt_lo[(size_t)CONV_DIM * DD];
__device__ __nv_bfloat16 g_Wzt_hi[(size_t)VAL_DIM * DD];      // [4096,2048]
__device__ __nv_bfloat16 g_Wzt_lo[(size_t)VAL_DIM * DD];
__device__ __nv_bfloat16 g_Woutt_hi[(size_t)DD * VAL_DIM];    // [2048,4096]
__device__ __nv_bfloat16 g_Woutt_lo[(size_t)DD * VAL_DIM];
__device__ __nv_bfloat16 g_chi[(size_t)MROWS * VAL_DIM];      // gated core hi
__device__ __nv_bfloat16 g_clo[(size_t)MROWS * VAL_DIM];      // gated core lo

// ================= PTX helpers (sm_103 baseline ISA only; NO 'a'-gated ops) =================
__device__ __forceinline__ uint32_t s2u(const void* p) {
    uint32_t a;
    asm("{ .reg .u64 t; cvta.to.shared.u64 t, %1; cvt.u32.u64 %0, t; }" : "=r"(a) : "l"(p));
    return a;
}
__device__ __forceinline__ void cp16(uint32_t s, const void* g) {
    asm volatile("cp.async.cg.shared.global [%0], [%1], 16;" :: "r"(s), "l"(g));
}
#define CP_COMMIT() asm volatile("cp.async.commit_group;" ::: "memory")
#define CP_WAIT(n)  asm volatile("cp.async.wait_group %0;" :: "n"(n) : "memory")

#define LDSM4(r, a) \
    asm volatile("ldmatrix.sync.aligned.m8n8.x4.shared.b16 {%0,%1,%2,%3}, [%4];" \
                 : "=r"((r)[0]), "=r"((r)[1]), "=r"((r)[2]), "=r"((r)[3]) : "r"(a))
#define MMA16816(d, a, b) \
    asm volatile("mma.sync.aligned.m16n8k16.row.col.f32.bf16.bf16.f32 " \
                 "{%0,%1,%2,%3},{%4,%5,%6,%7},{%8,%9},{%0,%1,%2,%3};" \
                 : "+f"((d)[0]), "+f"((d)[1]), "+f"((d)[2]), "+f"((d)[3]) \
                 : "r"((a)[0]), "r"((a)[1]), "r"((a)[2]), "r"((a)[3]), \
                   "r"((b)[0]), "r"((b)[1]))

// ================= split-bf16 HMMA GEMM =================
// C[M,N] = (Ahi+Alo)[M,K] . (Bhi+Blo)[N,K]^T  (drops lo.lo term)
// 128(M) x 256(N) tile, 8 warps (2x4, each 64x64), K-stage 32,
// 3-stage cp.async pipeline, one __syncthreads per stage.
#define STG_A  8192               // one A operand per stage (128 rows x 64B)
#define STG_B  16384              // one B operand per stage (256 rows x 64B)
#define STG_SZ (2*STG_A + 2*STG_B)  // 49152
#define NSTAGE 3
#define GSMEM  (NSTAGE * STG_SZ)    // 147456

__global__ void __launch_bounds__(256, 1) gemm_hmma_split(
    const __nv_bfloat16* __restrict__ Ah, const __nv_bfloat16* __restrict__ Al,
    const __nv_bfloat16* __restrict__ Bh, const __nv_bfloat16* __restrict__ Bl,
    float* __restrict__ C, int M, int N, int K)
{
    extern __shared__ __align__(16) char smraw[];
    const uint32_t sbase = s2u(smraw);
    const int tid = threadIdx.x;
    const int wid = tid >> 5, lane = tid & 31;
    const int bm = blockIdx.y * 128;
    const int bn = blockIdx.x * 256;
    const int wm = (wid & 1) * 64;   // warp row offset within tile
    const int wn = (wid >> 1) * 64;  // warp col offset within tile

    // swizzled smem byte offset for (row, 16B-chunk c in 0..3)
    auto swoff = [](int row, int c) -> uint32_t {
        return (uint32_t)(row * 64 + ((c ^ ((row >> 1) & 3)) << 4));
    };

    const int S = K / 32;

    auto load_stage = [&](int s) {
        const uint32_t sb = sbase + (uint32_t)(s % NSTAGE) * STG_SZ;
        const int k0 = s * 32;
        #pragma unroll
        for (int i = 0; i < 2; i++) {            // A: 512 16B-chunks
            int idx = tid + 256 * i;
            int row = idx >> 2, c = idx & 3;
            uint32_t off = swoff(row, c);
            size_t ga = (size_t)(bm + row) * K + k0 + c * 8;
            cp16(sb + off,         Ah + ga);
            cp16(sb + STG_A + off, Al + ga);
        }
        #pragma unroll
        for (int i = 0; i < 4; i++) {            // B: 1024 16B-chunks
            int idx = tid + 256 * i;
            int row = idx >> 2, c = idx & 3;
            uint32_t off = swoff(row, c);
            size_t gb = (size_t)(bn + row) * K + k0 + c * 8;
            cp16(sb + 2 * STG_A + off,         Bh + gb);
            cp16(sb + 2 * STG_A + STG_B + off, Bl + gb);
        }
        CP_COMMIT();
    };

    float acc[4][8][4];
    #pragma unroll
    for (int mi = 0; mi < 4; mi++)
        #pragma unroll
        for (int ni = 0; ni < 8; ni++)
            #pragma unroll
            for (int r = 0; r < 4; r++) acc[mi][ni][r] = 0.f;

    load_stage(0);
    load_stage(1);

    for (int s = 0; s < S; s++) {
        if (s + 1 < S) CP_WAIT(1);
        else           CP_WAIT(0);
        __syncthreads();
        if (s + 2 < S) load_stage(s + 2);   // buffer (s+2)%3 freed by compute(s-1)

        const uint32_t sb = sbase + (uint32_t)(s % NSTAGE) * STG_SZ;

        #pragma unroll
        for (int kk = 0; kk < 2; kk++) {
            uint32_t ah[4][4], alo[4][4];
            #pragma unroll
            for (int mi = 0; mi < 4; mi++) {
                int row = wm + mi * 16 + (lane & 15);
                int c   = (kk << 1) | (lane >> 4);
                uint32_t addr = sb + swoff(row, c);
                LDSM4(ah[mi],  addr);
                LDSM4(alo[mi], addr + STG_A);
            }
            #pragma unroll
            for (int half = 0; half < 2; half++) {
                // 4 n-tiles (8 cols each) per half; 2 LDSM4 load 2 n-tiles each
                uint32_t bh0[4], bh1[4], bl0[4], bl1[4];
                {
                    int row = wn + half * 32 + (lane >> 4) * 8 + (lane & 7);
                    int c   = (kk << 1) | ((lane >> 3) & 1);
                    uint32_t a0 = sb + 2 * STG_A + swoff(row, c);
                    uint32_t a1 = sb + 2 * STG_A + swoff(row + 16, c);
                    LDSM4(bh0, a0); LDSM4(bl0, a0 + STG_B);
                    LDSM4(bh1, a1); LDSM4(bl1, a1 + STG_B);
                }
                #pragma unroll
                for (int mi = 0; mi < 4; mi++) {
                    int nb = half * 4;
                    MMA16816(acc[mi][nb+0], ah[mi],  bh0 + 0);
                    MMA16816(acc[mi][nb+0], ah[mi],  bl0 + 0);
                    MMA16816(acc[mi][nb+0], alo[mi], bh0 + 0);
                    MMA16816(acc[mi][nb+1], ah[mi],  bh0 + 2);
                    MMA16816(acc[mi][nb+1], ah[mi],  bl0 + 2);
                    MMA16816(acc[mi][nb+1], alo[mi], bh0 + 2);
                    MMA16816(acc[mi][nb+2], ah[mi],  bh1 + 0);
                    MMA16816(acc[mi][nb+2], ah[mi],  bl1 + 0);
                    MMA16816(acc[mi][nb+2], alo[mi], bh1 + 0);
                    MMA16816(acc[mi][nb+3], ah[mi],  bh1 + 2);
                    MMA16816(acc[mi][nb+3], ah[mi],  bl1 + 2);
                    MMA16816(acc[mi][nb+3], alo[mi], bh1 + 2);
                }
            }
        }
    }

    // epilogue: c0,c1 -> (row, col..col+1); c2,c3 -> (row+8, col..col+1)
    #pragma unroll
    for (int mi = 0; mi < 4; mi++) {
        #pragma unroll
        for (int ni = 0; ni < 8; ni++) {
            int row = bm + wm + mi * 16 + (lane >> 2);
            int col = bn + wn + ni * 8 + (lane & 3) * 2;
            float* p = C + (size_t)row * N + col;
            *(float2*)p = make_float2(acc[mi][ni][0], acc[mi][ni][1]);
            *(float2*)(p + (size_t)8 * N) = make_float2(acc[mi][ni][2], acc[mi][ni][3]);
        }
    }
}

// ================= operand prep =================
__global__ void __launch_bounds__(256) split_bf16(
    const float4* __restrict__ x, __nv_bfloat16* __restrict__ hi,
    __nv_bfloat16* __restrict__ lo, int n4)
{
    int i = blockIdx.x * 256 + threadIdx.x;
    if (i >= n4) return;
    float4 v = x[i];
    __nv_bfloat16 h0 = __float2bfloat16(v.x), h1 = __float2bfloat16(v.y);
    __nv_bfloat16 h2 = __float2bfloat16(v.z), h3 = __float2bfloat16(v.w);
    __nv_bfloat162* H = (__nv_bfloat162*)(hi) + 2 * (size_t)i;
    __nv_bfloat162* L = (__nv_bfloat162*)(lo) + 2 * (size_t)i;
    H[0] = __nv_bfloat162(h0, h1);
    H[1] = __nv_bfloat162(h2, h3);
    L[0] = __nv_bfloat162(__float2bfloat16(v.x - __bfloat162float(h0)),
                          __float2bfloat16(v.y - __bfloat162float(h1)));
    L[1] = __nv_bfloat162(__float2bfloat16(v.z - __bfloat162float(h2)),
                          __float2bfloat16(v.w - __bfloat162float(h3)));
}

// transpose W[R,C] fp32 -> out[C,R] bf16 hi/lo
__global__ void __launch_bounds__(256) transpose_split(
    const float* __restrict__ W, __nv_bfloat16* __restrict__ hi,
    __nv_bfloat16* __restrict__ lo, int R, int C)
{
    __shared__ float t[32][33];
    const int c0 = blockIdx.x * 32, r0 = blockIdx.y * 32;
    const int tx = threadIdx.x & 31;
    const int ty0 = threadIdx.x >> 5;
    #pragma unroll
    for (int i = 0; i < 32; i += 8)
        t[ty0 + i][tx] = W[(size_t)(r0 + ty0 + i) * C + c0 + tx];
    __syncthreads();
    #pragma unroll
    for (int i = 0; i < 32; i += 8) {
        float v = t[tx][ty0 + i];
        __nv_bfloat16 h = __float2bfloat16(v);
        size_t o = (size_t)(c0 + ty0 + i) * R + r0 + tx;
        hi[o] = h;
        lo[o] = __float2bfloat16(v - __bfloat162float(h));
    }
}

// ---------------- skinny GEMM: b = H@W_b, a = H@W_a ----------------
__global__ void __launch_bounds__(64) gemm_ba(
    const float* __restrict__ H, const float* __restrict__ Wb,
    const float* __restrict__ Wa, float* __restrict__ ob, float* __restrict__ oa)
{
    const int m0 = blockIdx.x * 8;
    const int t  = threadIdx.x;
    const float* W = (t < 32) ? Wb : Wa;
    const int colw = t & 31;
    float s[8];
    #pragma unroll
    for (int r = 0; r < 8; r++) s[r] = 0.f;
    for (int k = 0; k < DD; k++) {
        float wv = W[(size_t)k * 32 + colw];
        #pragma unroll
        for (int r = 0; r < 8; r++)
            s[r] = fmaf(H[(size_t)(m0 + r) * DD + k], wv, s[r]);
    }
    #pragma unroll
    for (int r = 0; r < 8; r++) {
        if (t < 32) ob[(size_t)(m0 + r) * 32 + colw] = s[r];
        else        oa[(size_t)(m0 + r) * 32 + colw] = s[r];
    }
}

// ---------------- causal depthwise conv (K=4) + SiLU, float4 ----------------
__global__ void __launch_bounds__(256) conv_silu4(
    const float4* __restrict__ x, const float4* __restrict__ w, float4* __restrict__ y)
{
    const size_t i = (size_t)blockIdx.x * 256 + threadIdx.x;  // float4 idx < MROWS*2048
    const int c4 = (int)(i & 2047);
    const int l  = (int)((i >> 11) & (LL - 1));
    const float4 zero = make_float4(0.f, 0.f, 0.f, 0.f);
    float4 x0 = x[i];
    float4 x1 = (l >= 1) ? x[i - 2048] : zero;
    float4 x2 = (l >= 2) ? x[i - 4096] : zero;
    float4 x3 = (l >= 3) ? x[i - 6144] : zero;
    float4 w0 = w[4 * c4 + 0], w1 = w[4 * c4 + 1], w2 = w[4 * c4 + 2], w3 = w[4 * c4 + 3];
    float4 a;
    a.x = fmaf(w0.x, x3.x, fmaf(w0.y, x2.x, fmaf(w0.z, x1.x, w0.w * x0.x)));
    a.y = fmaf(w1.x, x3.y, fmaf(w1.y, x2.y, fmaf(w1.z, x1.y, w1.w * x0.y)));
    a.z = fmaf(w2.x, x3.z, fmaf(w2.y, x2.z, fmaf(w2.z, x1.z, w2.w * x0.z)));
    a.w = fmaf(w3.x, x3.w, fmaf(w3.y, x2.w, fmaf(w3.z, x1.w, w3.w * x0.w)));
    a.x = a.x / (1.f + __expf(-a.x));
    a.y = a.y / (1.f + __expf(-a.y));
    a.z = a.z / (1.f + __expf(-a.z));
    a.w = a.w / (1.f + __expf(-a.w));
    y[i] = a;
}

// ---------------- q/k l2norm (+ q scale) ----------------
__global__ void __launch_bounds__(256) qk_norm(
    const float* __restrict__ conv, float* __restrict__ qn, float* __restrict__ kn)
{
    const int warp = (blockIdx.x * 256 + threadIdx.x) >> 5;
    const int lane = threadIdx.x & 31;
    const int bl = warp >> 4;
    const int kh = warp & 15;
    const float* qp = conv + (size_t)bl * CONV_DIM + kh * DK + lane * 4;
    const float* kp = qp + KEY_DIM;
    float4 q4 = *(const float4*)qp;
    float4 k4 = *(const float4*)kp;
    float sq = q4.x*q4.x + q4.y*q4.y + q4.z*q4.z + q4.w*q4.w;
    float sk = k4.x*k4.x + k4.y*k4.y + k4.z*k4.z + k4.w*k4.w;
    #pragma unroll
    for (int d = 16; d >= 1; d >>= 1) {
        sq += __shfl_xor_sync(0xffffffffu, sq, d);
        sk += __shfl_xor_sync(0xffffffffu, sk, d);
    }
    const float qscale = rsqrtf(sq + 1e-6f) * 0.08838834764831845f;
    const float kscale = rsqrtf(sk + 1e-6f);
    float* qo = qn + (size_t)warp * DK + lane * 4;
    float* ko = kn + (size_t)warp * DK + lane * 4;
    *(float4*)qo = make_float4(q4.x*qscale, q4.y*qscale, q4.z*qscale, q4.w*qscale);
    *(float4*)ko = make_float4(k4.x*kscale, k4.y*kscale, k4.z*kscale, k4.w*kscale);
}

// ---------------- beta/g ----------------
__global__ void __launch_bounds__(256) betag(
    const float* __restrict__ bb, const float* __restrict__ aa,
    const float* __restrict__ A_log, const float* __restrict__ dt_bias,
    float* __restrict__ beta, float* __restrict__ g)
{
    const int i = blockIdx.x * 256 + threadIdx.x;
    const int h = i & (HV - 1);
    float bv = bb[i];
    float av = aa[i] + dt_bias[h];
    beta[i] = 1.f / (1.f + expf(-bv));
    float sp = (av > 20.f) ? av : log1pf(expf(av));
    g[i] = -expf(A_log[h]) * sp;
}

// ---------------- gated delta-rule recurrence ----------------
// grid: B*HV*2 = 128 CTAs (each: 64 of 128 V-cols of one (b,h) state).
// block: 256 threads (8 warps). Thread owns a 32-row quarter-column of S.
// warp w covers 8 cols x 4 quarters; q = lane>>3 selects quarter.
// Reduction over quarters: shfl_xor 8, then 16. Smem quarter stride padded
// to 36 floats (144B) for conflict-free LDS.128.
__global__ void __launch_bounds__(256) recurrence(
    const float* __restrict__ qn, const float* __restrict__ kn,
    const float* __restrict__ conv, const float* __restrict__ gg,
    const float* __restrict__ bbeta, float* __restrict__ core)
{
    const int blk = blockIdx.x;
    const int b  = blk >> 6;
    const int h  = (blk >> 1) & 31;
    const int vh = blk & 1;
    const int kh = h >> 1;
    const int tid = threadIdx.x;
    const int w = tid >> 5, lane = tid & 31;
    const int q = lane >> 3;               // quarter 0..3
    const int col = vh * 64 + w * 8 + (lane & 7);
    const int pb = q * 36;                 // padded float offset of quarter

    __shared__ __align__(16) float qs[2][148];
    __shared__ __align__(16) float ks[2][148];

    float S[32];
    #pragma unroll
    for (int i = 0; i < 32; i++) S[i] = 0.f;

    const bool ldr = (tid < 128);
    const int wi = ((tid >> 5) & 3) * 36 + (tid & 31);   // padded write idx for tid<128

    const float* qptr = qn + ((size_t)b * LL * HK + kh) * DK + (tid & 127);
    const float* kptr = kn + ((size_t)b * LL * HK + kh) * DK + (tid & 127);
    const float* vptr = conv + (size_t)b * LL * CONV_DIM + 2 * KEY_DIM + h * DV + col;
    const float* gptr = gg    + (size_t)b * LL * HV + h;
    const float* bptr = bbeta + (size_t)b * LL * HV + h;
    float* optr = core + ((size_t)b * LL * HV + h) * DV + col;

    float qN = 0.f, kN = 0.f;
    if (ldr) { qN = qptr[0]; kN = kptr[0]; }
    float vc = vptr[0], gc = gptr[0], bc = bptr[0];
    if (ldr) { qs[0][wi] = qN; ks[0][wi] = kN; }
    __syncthreads();

    for (int l = 0; l < LL; l++) {
        const int cur = l & 1, nxt = cur ^ 1;
        float vN = vc, gN = gc, bN = bc;
        if (l + 1 < LL) {
            size_t o = (size_t)(l + 1);
            if (ldr) {
                qN = qptr[o * (HK * DK)];
                kN = kptr[o * (HK * DK)];
            }
            vN = vptr[o * CONV_DIM];
            gN = gptr[o * HV];
            bN = bptr[o * HV];
        }

        const float eg = __expf(gc);
        const float* kcur = &ks[cur][pb];
        const float* qcur = &qs[cur][pb];

        // pass 1: kv = k . S_old (quarter partial)
        float a0 = 0.f, a1 = 0.f, a2 = 0.f, a3 = 0.f;
        #pragma unroll
        for (int i = 0; i < 8; i++) {
            float4 k4 = *(const float4*)(kcur + 4 * i);
            a0 = fmaf(k4.x, S[4*i+0], a0);
            a1 = fmaf(k4.y, S[4*i+1], a1);
            a2 = fmaf(k4.z, S[4*i+2], a2);
            a3 = fmaf(k4.w, S[4*i+3], a3);
        }
        float kv = (a0 + a1) + (a2 + a3);
        kv += __shfl_xor_sync(0xffffffffu, kv, 8);
        kv += __shfl_xor_sync(0xffffffffu, kv, 16);
        const float delta = (vc - eg * kv) * bc;

        // pass 2: S = eg*S + k*delta ; o = q . S (quarter partial)
        float o0 = 0.f, o1 = 0.f, o2 = 0.f, o3 = 0.f;
        #pragma unroll
        for (int i = 0; i < 8; i++) {
            float4 k4 = *(const float4*)(kcur + 4 * i);
            float4 q4 = *(const float4*)(qcur + 4 * i);
            S[4*i+0] = fmaf(eg, S[4*i+0], k4.x * delta);
            S[4*i+1] = fmaf(eg, S[4*i+1], k4.y * delta);
            S[4*i+2] = fmaf(eg, S[4*i+2], k4.z * delta);
            S[4*i+3] = fmaf(eg, S[4*i+3], k4.w * delta);
            o0 = fmaf(q4.x, S[4*i+0], o0);
            o1 = fmaf(q4.y, S[4*i+1], o1);
            o2 = fmaf(q4.z, S[4*i+2], o2);
            o3 = fmaf(q4.w, S[4*i+3], o3);
        }
        float o = (o0 + o1) + (o2 + o3);
        o += __shfl_xor_sync(0xffffffffu, o, 8);
        o += __shfl_xor_sync(0xffffffffu, o, 16);
        if (q == 0) optr[(size_t)l * VAL_DIM] = o;

        if (ldr) { qs[nxt][wi] = qN; ks[nxt][wi] = kN; }
        vc = vN; gc = gN; bc = bN;
        __syncthreads();
    }
}

// ---------------- gated RMSNorm -> bf16 hi/lo ----------------
__global__ void __launch_bounds__(256) gated_rmsnorm_split(
    const float* __restrict__ core, const float* __restrict__ z,
    const float* __restrict__ nw,
    __nv_bfloat16* __restrict__ chi, __nv_bfloat16* __restrict__ clo)
{
    const int warp = (blockIdx.x * 256 + threadIdx.x) >> 5;
    const int lane = threadIdx.x & 31;
    const size_t base = (size_t)warp * DV + lane * 4;

    float4 c4 = *(const float4*)(core + base);
    float4 z4 = *(const float4*)(z + base);
    float gx = c4.x * (z4.x / (1.f + expf(-z4.x)));
    float gy = c4.y * (z4.y / (1.f + expf(-z4.y)));
    float gz = c4.z * (z4.z / (1.f + expf(-z4.z)));
    float gw = c4.w * (z4.w / (1.f + expf(-z4.w)));
    float ss = gx*gx + gy*gy + gz*gz + gw*gw;
    #pragma unroll
    for (int d = 16; d >= 1; d >>= 1) ss += __shfl_xor_sync(0xffffffffu, ss, d);
    const float scale = rsqrtf(ss * (1.f / DV) + 1e-6f);
    float4 w4 = *(const float4*)(nw + lane * 4);
    float v0 = gx * scale * w4.x, v1 = gy * scale * w4.y;
    float v2 = gz * scale * w4.z, v3 = gw * scale * w4.w;

    __nv_bfloat16 h0 = __float2bfloat16(v0), h1 = __float2bfloat16(v1);
    __nv_bfloat16 h2 = __float2bfloat16(v2), h3 = __float2bfloat16(v3);
    __nv_bfloat162* H = (__nv_bfloat162*)(chi + base);
    __nv_bfloat162* L = (__nv_bfloat162*)(clo + base);
    H[0] = __nv_bfloat162(h0, h1);
    H[1] = __nv_bfloat162(h2, h3);
    L[0] = __nv_bfloat162(__float2bfloat16(v0 - __bfloat162float(h0)),
                          __float2bfloat16(v1 - __bfloat162float(h1)));
    L[1] = __nv_bfloat162(__float2bfloat16(v2 - __bfloat162float(h2)),
                          __float2bfloat16(v3 - __bfloat162float(h3)));
}

// ---------------- launch ----------------
extern "C" void kernel_launch(void* const* d_in, const int* in_sizes, int n_in,
                              void* d_out, int out_size)
{
    const float* H       = (const float*)d_in[0];
    const float* W_qkv   = (const float*)d_in[1];
    const float* W_z     = (const float*)d_in[2];
    const float* W_b     = (const float*)d_in[3];
    const float* W_a     = (const float*)d_in[4];
    const float* conv_w  = (const float*)d_in[5];
    const float* dt_bias = (const float*)d_in[6];
    const float* A_log   = (const float*)d_in[7];
    const float* norm_w  = (const float*)d_in[8];
    const float* W_out   = (const float*)d_in[9];
    float* out = (float*)d_out;

    float *mixed, *convb, *z, *core, *qn, *kn, *bb, *aa, *beta, *g;
    cudaGetSymbolAddress((void**)&mixed, g_mixed);
    cudaGetSymbolAddress((void**)&convb, g_conv);
    cudaGetSymbolAddress((void**)&z,     g_z);
    cudaGetSymbolAddress((void**)&core,  g_core);
    cudaGetSymbolAddress((void**)&qn,    g_qn);
    cudaGetSymbolAddress((void**)&kn,    g_kn);
    cudaGetSymbolAddress((void**)&bb,    g_bv);
    cudaGetSymbolAddress((void**)&aa,    g_av);
    cudaGetSymbolAddress((void**)&beta,  g_beta);
    cudaGetSymbolAddress((void**)&g,     g_g);

    __nv_bfloat16 *Hhi, *Hlo, *Wqh, *Wql, *Wzh, *Wzl, *Woh, *Wol, *chi, *clo;
    cudaGetSymbolAddress((void**)&Hhi, g_Hhi);
    cudaGetSymbolAddress((void**)&Hlo, g_Hlo);
    cudaGetSymbolAddress((void**)&Wqh, g_Wqkvt_hi);
    cudaGetSymbolAddress((void**)&Wql, g_Wqkvt_lo);
    cudaGetSymbolAddress((void**)&Wzh, g_Wzt_hi);
    cudaGetSymbolAddress((void**)&Wzl, g_Wzt_lo);
    cudaGetSymbolAddress((void**)&Woh, g_Woutt_hi);
    cudaGetSymbolAddress((void**)&Wol, g_Woutt_lo);
    cudaGetSymbolAddress((void**)&chi, g_chi);
    cudaGetSymbolAddress((void**)&clo, g_clo);

    cudaFuncSetAttribute(gemm_hmma_split, cudaFuncAttributeMaxDynamicSharedMemorySize, GSMEM);

    // 0) operand prep: split H, transpose+split weights
    split_bf16<<<(MROWS * DD / 4) / 256, 256>>>((const float4*)H, Hhi, Hlo, MROWS * DD / 4);
    transpose_split<<<dim3(CONV_DIM / 32, DD / 32), 256>>>(W_qkv, Wqh, Wql, DD, CONV_DIM);
    transpose_split<<<dim3(VAL_DIM / 32, DD / 32), 256>>>(W_z, Wzh, Wzl, DD, VAL_DIM);
    transpose_split<<<dim3(DD / 32, VAL_DIM / 32), 256>>>(W_out, Woh, Wol, VAL_DIM, DD);

    // 1) big projections (HMMA bf16 split)
    gemm_hmma_split<<<dim3(CONV_DIM / 256, MROWS / 128), 256, GSMEM>>>(
        Hhi, Hlo, Wqh, Wql, mixed, MROWS, CONV_DIM, DD);
    gemm_hmma_split<<<dim3(VAL_DIM / 256, MROWS / 128), 256, GSMEM>>>(
        Hhi, Hlo, Wzh, Wzl, z, MROWS, VAL_DIM, DD);
    gemm_ba<<<MROWS / 8, 64>>>(H, W_b, W_a, bb, aa);

    // 2) conv + activation + norms
    conv_silu4<<<(MROWS * (size_t)CONV_DIM / 4) / 256, 256>>>(
        (const float4*)mixed, (const float4*)conv_w, (float4*)convb);
    qk_norm<<<(MROWS * HK) / 8, 256>>>(convb, qn, kn);
    betag<<<(MROWS * HV) / 256, 256>>>(bb, aa, A_log, dt_bias, beta, g);

    // 3) sequential gated delta-rule scan
    recurrence<<<BB * HV * 2, 256>>>(qn, kn, convb, g, beta, core);

    // 4) gated RMSNorm (-> bf16 hi/lo) + output projection (HMMA bf16 split)
    gated_rmsnorm_split<<<(MROWS * HV) / 8, 256>>>(core, z, norm_w, chi, clo);
    gemm_hmma_split<<<dim3(DD / 256, MROWS / 128), 256, GSMEM>>>(
        chi, clo, Woh, Wol, out, MROWS, DD, VAL_DIM);
}

// round 11
// speedup vs baseline: 2.2024x; 1.0976x over previous
#include <cuda_runtime.h>
#include <cuda_bf16.h>
#include <cstdint>
#include <cstdio>

// ---------------- problem constants ----------------
#define BB   2
#define LL   2048
#define DD   2048
#define HV   32
#define HK   16
#define DK   128
#define DV   128
#define KCONV 4
#define KEY_DIM  2048
#define VAL_DIM  4096
#define CONV_DIM 8192
#define MROWS (BB*LL)          // 4096

// ---------------- scratch (static device globals; no runtime alloc) ----------------
__device__ float g_mixed[(size_t)MROWS * CONV_DIM];   // qkv mix (fp32)
__device__ float g_conv [(size_t)MROWS * CONV_DIM];   // post conv+silu
__device__ float g_z    [(size_t)MROWS * VAL_DIM];    // gate
__device__ float g_core [(size_t)MROWS * VAL_DIM];    // scan output (fp32)
__device__ float g_qn   [(size_t)MROWS * HK * DK];
__device__ float g_kn   [(size_t)MROWS * HK * DK];
__device__ float g_bv   [(size_t)MROWS * HV];
__device__ float g_av   [(size_t)MROWS * HV];
__device__ float g_beta [(size_t)MROWS * HV];
__device__ float g_g    [(size_t)MROWS * HV];

// bf16 split operands
__device__ __nv_bfloat16 g_Hhi[(size_t)MROWS * DD];
__device__ __nv_bfloat16 g_Hlo[(size_t)MROWS * DD];
__device__ __nv_bfloat16 g_Wqkvt_hi[(size_t)CONV_DIM * DD];   // [N,K] = [8192,2048]
__device__ __nv_bfloat16 g_Wqkvt_lo[(size_t)CONV_DIM * DD];
__device__ __nv_bfloat16 g_Wzt_hi[(size_t)VAL_DIM * DD];      // [4096,2048]
__device__ __nv_bfloat16 g_Wzt_lo[(size_t)VAL_DIM * DD];
__device__ __nv_bfloat16 g_Woutt_hi[(size_t)DD * VAL_DIM];    // [2048,4096]
__device__ __nv_bfloat16 g_Woutt_lo[(size_t)DD * VAL_DIM];
__device__ __nv_bfloat16 g_chi[(size_t)MROWS * VAL_DIM];      // gated core hi
__device__ __nv_bfloat16 g_clo[(size_t)MROWS * VAL_DIM];      // gated core lo

// ================= PTX helpers (sm_103 baseline ISA only; NO 'a'-gated ops) =================
__device__ __forceinline__ uint32_t s2u(const void* p) {
    uint32_t a;
    asm("{ .reg .u64 t; cvta.to.shared.u64 t, %1; cvt.u32.u64 %0, t; }" : "=r"(a) : "l"(p));
    return a;
}
__device__ __forceinline__ void cp16(uint32_t s, const void* g) {
    asm volatile("cp.async.cg.shared.global [%0], [%1], 16;" :: "r"(s), "l"(g));
}
#define CP_COMMIT() asm volatile("cp.async.commit_group;" ::: "memory")
#define CP_WAIT(n)  asm volatile("cp.async.wait_group %0;" :: "n"(n) : "memory")

#define LDSM4(r, a) \
    asm volatile("ldmatrix.sync.aligned.m8n8.x4.shared.b16 {%0,%1,%2,%3}, [%4];" \
                 : "=r"((r)[0]), "=r"((r)[1]), "=r"((r)[2]), "=r"((r)[3]) : "r"(a))
#define MMA16816(d, a, b) \
    asm volatile("mma.sync.aligned.m16n8k16.row.col.f32.bf16.bf16.f32 " \
                 "{%0,%1,%2,%3},{%4,%5,%6,%7},{%8,%9},{%0,%1,%2,%3};" \
                 : "+f"((d)[0]), "+f"((d)[1]), "+f"((d)[2]), "+f"((d)[3]) \
                 : "r"((a)[0]), "r"((a)[1]), "r"((a)[2]), "r"((a)[3]), \
                   "r"((b)[0]), "r"((b)[1]))

// packed f32x2 (sm_100-family PTX; FFMA2 in SASS — 2x fp32 fma throughput)
typedef unsigned long long ull;
#define FMA2(d, a, b, c) asm("fma.rn.f32x2 %0, %1, %2, %3;" : "=l"(d) : "l"(a), "l"(b), "l"(c))
#define MUL2(d, a, b)    asm("mul.rn.f32x2 %0, %1, %2;"     : "=l"(d) : "l"(a), "l"(b))
#define ADD2(d, a, b)    asm("add.rn.f32x2 %0, %1, %2;"     : "=l"(d) : "l"(a), "l"(b))
__device__ __forceinline__ ull pack2(float x) {
    uint32_t b = __float_as_uint(x);
    return ((ull)b << 32) | (ull)b;
}
__device__ __forceinline__ float lo_f(ull v) { return __uint_as_float((uint32_t)v); }
__device__ __forceinline__ float hi_f(ull v) { return __uint_as_float((uint32_t)(v >> 32)); }

// ================= split-bf16 HMMA GEMM =================
// C[M,N] = (Ahi+Alo)[M,K] . (Bhi+Blo)[N,K]^T  (drops lo.lo term)
// 128(M) x 256(N) tile, 8 warps (2x4, each 64x64), K-stage 32,
// 3-stage cp.async pipeline, one __syncthreads per stage.
#define STG_A  8192               // one A operand per stage (128 rows x 64B)
#define STG_B  16384              // one B operand per stage (256 rows x 64B)
#define STG_SZ (2*STG_A + 2*STG_B)  // 49152
#define NSTAGE 3
#define GSMEM  (NSTAGE * STG_SZ)    // 147456

__global__ void __launch_bounds__(256, 1) gemm_hmma_split(
    const __nv_bfloat16* __restrict__ Ah, const __nv_bfloat16* __restrict__ Al,
    const __nv_bfloat16* __restrict__ Bh, const __nv_bfloat16* __restrict__ Bl,
    float* __restrict__ C, int M, int N, int K)
{
    extern __shared__ __align__(16) char smraw[];
    const uint32_t sbase = s2u(smraw);
    const int tid = threadIdx.x;
    const int wid = tid >> 5, lane = tid & 31;
    const int bm = blockIdx.y * 128;
    const int bn = blockIdx.x * 256;
    const int wm = (wid & 1) * 64;   // warp row offset within tile
    const int wn = (wid >> 1) * 64;  // warp col offset within tile

    // swizzled smem byte offset for (row, 16B-chunk c in 0..3)
    auto swoff = [](int row, int c) -> uint32_t {
        return (uint32_t)(row * 64 + ((c ^ ((row >> 1) & 3)) << 4));
    };

    const int S = K / 32;

    auto load_stage = [&](int s) {
        const uint32_t sb = sbase + (uint32_t)(s % NSTAGE) * STG_SZ;
        const int k0 = s * 32;
        #pragma unroll
        for (int i = 0; i < 2; i++) {            // A: 512 16B-chunks
            int idx = tid + 256 * i;
            int row = idx >> 2, c = idx & 3;
            uint32_t off = swoff(row, c);
            size_t ga = (size_t)(bm + row) * K + k0 + c * 8;
            cp16(sb + off,         Ah + ga);
            cp16(sb + STG_A + off, Al + ga);
        }
        #pragma unroll
        for (int i = 0; i < 4; i++) {            // B: 1024 16B-chunks
            int idx = tid + 256 * i;
            int row = idx >> 2, c = idx & 3;
            uint32_t off = swoff(row, c);
            size_t gb = (size_t)(bn + row) * K + k0 + c * 8;
            cp16(sb + 2 * STG_A + off,         Bh + gb);
            cp16(sb + 2 * STG_A + STG_B + off, Bl + gb);
        }
        CP_COMMIT();
    };

    float acc[4][8][4];
    #pragma unroll
    for (int mi = 0; mi < 4; mi++)
        #pragma unroll
        for (int ni = 0; ni < 8; ni++)
            #pragma unroll
            for (int r = 0; r < 4; r++) acc[mi][ni][r] = 0.f;

    load_stage(0);
    load_stage(1);

    for (int s = 0; s < S; s++) {
        if (s + 1 < S) CP_WAIT(1);
        else           CP_WAIT(0);
        __syncthreads();
        if (s + 2 < S) load_stage(s + 2);   // buffer (s+2)%3 freed by compute(s-1)

        const uint32_t sb = sbase + (uint32_t)(s % NSTAGE) * STG_SZ;

        #pragma unroll
        for (int kk = 0; kk < 2; kk++) {
            uint32_t ah[4][4], alo[4][4];
            #pragma unroll
            for (int mi = 0; mi < 4; mi++) {
                int row = wm + mi * 16 + (lane & 15);
                int c   = (kk << 1) | (lane >> 4);
                uint32_t addr = sb + swoff(row, c);
                LDSM4(ah[mi],  addr);
                LDSM4(alo[mi], addr + STG_A);
            }
            #pragma unroll
            for (int half = 0; half < 2; half++) {
                // 4 n-tiles (8 cols each) per half; 2 LDSM4 load 2 n-tiles each
                uint32_t bh0[4], bh1[4], bl0[4], bl1[4];
                {
                    int row = wn + half * 32 + (lane >> 4) * 8 + (lane & 7);
                    int c   = (kk << 1) | ((lane >> 3) & 1);
                    uint32_t a0 = sb + 2 * STG_A + swoff(row, c);
                    uint32_t a1 = sb + 2 * STG_A + swoff(row + 16, c);
                    LDSM4(bh0, a0); LDSM4(bl0, a0 + STG_B);
                    LDSM4(bh1, a1); LDSM4(bl1, a1 + STG_B);
                }
                #pragma unroll
                for (int mi = 0; mi < 4; mi++) {
                    int nb = half * 4;
                    MMA16816(acc[mi][nb+0], ah[mi],  bh0 + 0);
                    MMA16816(acc[mi][nb+0], ah[mi],  bl0 + 0);
                    MMA16816(acc[mi][nb+0], alo[mi], bh0 + 0);
                    MMA16816(acc[mi][nb+1], ah[mi],  bh0 + 2);
                    MMA16816(acc[mi][nb+1], ah[mi],  bl0 + 2);
                    MMA16816(acc[mi][nb+1], alo[mi], bh0 + 2);
                    MMA16816(acc[mi][nb+2], ah[mi],  bh1 + 0);
                    MMA16816(acc[mi][nb+2], ah[mi],  bl1 + 0);
                    MMA16816(acc[mi][nb+2], alo[mi], bh1 + 0);
                    MMA16816(acc[mi][nb+3], ah[mi],  bh1 + 2);
                    MMA16816(acc[mi][nb+3], ah[mi],  bl1 + 2);
                    MMA16816(acc[mi][nb+3], alo[mi], bh1 + 2);
                }
            }
        }
    }

    // epilogue: c0,c1 -> (row, col..col+1); c2,c3 -> (row+8, col..col+1)
    #pragma unroll
    for (int mi = 0; mi < 4; mi++) {
        #pragma unroll
        for (int ni = 0; ni < 8; ni++) {
            int row = bm + wm + mi * 16 + (lane >> 2);
            int col = bn + wn + ni * 8 + (lane & 3) * 2;
            float* p = C + (size_t)row * N + col;
            *(float2*)p = make_float2(acc[mi][ni][0], acc[mi][ni][1]);
            *(float2*)(p + (size_t)8 * N) = make_float2(acc[mi][ni][2], acc[mi][ni][3]);
        }
    }
}

// ================= operand prep =================
__global__ void __launch_bounds__(256) split_bf16(
    const float4* __restrict__ x, __nv_bfloat16* __restrict__ hi,
    __nv_bfloat16* __restrict__ lo, int n4)
{
    int i = blockIdx.x * 256 + threadIdx.x;
    if (i >= n4) return;
    float4 v = x[i];
    __nv_bfloat16 h0 = __float2bfloat16(v.x), h1 = __float2bfloat16(v.y);
    __nv_bfloat16 h2 = __float2bfloat16(v.z), h3 = __float2bfloat16(v.w);
    __nv_bfloat162* H = (__nv_bfloat162*)(hi) + 2 * (size_t)i;
    __nv_bfloat162* L = (__nv_bfloat162*)(lo) + 2 * (size_t)i;
    H[0] = __nv_bfloat162(h0, h1);
    H[1] = __nv_bfloat162(h2, h3);
    L[0] = __nv_bfloat162(__float2bfloat16(v.x - __bfloat162float(h0)),
                          __float2bfloat16(v.y - __bfloat162float(h1)));
    L[1] = __nv_bfloat162(__float2bfloat16(v.z - __bfloat162float(h2)),
                          __float2bfloat16(v.w - __bfloat162float(h3)));
}

// transpose W[R,C] fp32 -> out[C,R] bf16 hi/lo
__global__ void __launch_bounds__(256) transpose_split(
    const float* __restrict__ W, __nv_bfloat16* __restrict__ hi,
    __nv_bfloat16* __restrict__ lo, int R, int C)
{
    __shared__ float t[32][33];
    const int c0 = blockIdx.x * 32, r0 = blockIdx.y * 32;
    const int tx = threadIdx.x & 31;
    const int ty0 = threadIdx.x >> 5;
    #pragma unroll
    for (int i = 0; i < 32; i += 8)
        t[ty0 + i][tx] = W[(size_t)(r0 + ty0 + i) * C + c0 + tx];
    __syncthreads();
    #pragma unroll
    for (int i = 0; i < 32; i += 8) {
        float v = t[tx][ty0 + i];
        __nv_bfloat16 h = __float2bfloat16(v);
        size_t o = (size_t)(c0 + ty0 + i) * R + r0 + tx;
        hi[o] = h;
        lo[o] = __float2bfloat16(v - __bfloat162float(h));
    }
}

// ---------------- skinny GEMM: b = H@W_b, a = H@W_a ----------------
__global__ void __launch_bounds__(64) gemm_ba(
    const float* __restrict__ H, const float* __restrict__ Wb,
    const float* __restrict__ Wa, float* __restrict__ ob, float* __restrict__ oa)
{
    const int m0 = blockIdx.x * 8;
    const int t  = threadIdx.x;
    const float* W = (t < 32) ? Wb : Wa;
    const int colw = t & 31;
    float s[8];
    #pragma unroll
    for (int r = 0; r < 8; r++) s[r] = 0.f;
    for (int k = 0; k < DD; k++) {
        float wv = W[(size_t)k * 32 + colw];
        #pragma unroll
        for (int r = 0; r < 8; r++)
            s[r] = fmaf(H[(size_t)(m0 + r) * DD + k], wv, s[r]);
    }
    #pragma unroll
    for (int r = 0; r < 8; r++) {
        if (t < 32) ob[(size_t)(m0 + r) * 32 + colw] = s[r];
        else        oa[(size_t)(m0 + r) * 32 + colw] = s[r];
    }
}

// ---------------- causal depthwise conv (K=4) + SiLU, float4 ----------------
__global__ void __launch_bounds__(256) conv_silu4(
    const float4* __restrict__ x, const float4* __restrict__ w, float4* __restrict__ y)
{
    const size_t i = (size_t)blockIdx.x * 256 + threadIdx.x;  // float4 idx < MROWS*2048
    const int c4 = (int)(i & 2047);
    const int l  = (int)((i >> 11) & (LL - 1));
    const float4 zero = make_float4(0.f, 0.f, 0.f, 0.f);
    float4 x0 = x[i];
    float4 x1 = (l >= 1) ? x[i - 2048] : zero;
    float4 x2 = (l >= 2) ? x[i - 4096] : zero;
    float4 x3 = (l >= 3) ? x[i - 6144] : zero;
    float4 w0 = w[4 * c4 + 0], w1 = w[4 * c4 + 1], w2 = w[4 * c4 + 2], w3 = w[4 * c4 + 3];
    float4 a;
    a.x = fmaf(w0.x, x3.x, fmaf(w0.y, x2.x, fmaf(w0.z, x1.x, w0.w * x0.x)));
    a.y = fmaf(w1.x, x3.y, fmaf(w1.y, x2.y, fmaf(w1.z, x1.y, w1.w * x0.y)));
    a.z = fmaf(w2.x, x3.z, fmaf(w2.y, x2.z, fmaf(w2.z, x1.z, w2.w * x0.z)));
    a.w = fmaf(w3.x, x3.w, fmaf(w3.y, x2.w, fmaf(w3.z, x1.w, w3.w * x0.w)));
    a.x = a.x / (1.f + __expf(-a.x));
    a.y = a.y / (1.f + __expf(-a.y));
    a.z = a.z / (1.f + __expf(-a.z));
    a.w = a.w / (1.f + __expf(-a.w));
    y[i] = a;
}

// ---------------- q/k l2norm (+ q scale) ----------------
__global__ void __launch_bounds__(256) qk_norm(
    const float* __restrict__ conv, float* __restrict__ qn, float* __restrict__ kn)
{
    const int warp = (blockIdx.x * 256 + threadIdx.x) >> 5;
    const int lane = threadIdx.x & 31;
    const int bl = warp >> 4;
    const int kh = warp & 15;
    const float* qp = conv + (size_t)bl * CONV_DIM + kh * DK + lane * 4;
    const float* kp = qp + KEY_DIM;
    float4 q4 = *(const float4*)qp;
    float4 k4 = *(const float4*)kp;
    float sq = q4.x*q4.x + q4.y*q4.y + q4.z*q4.z + q4.w*q4.w;
    float sk = k4.x*k4.x + k4.y*k4.y + k4.z*k4.z + k4.w*k4.w;
    #pragma unroll
    for (int d = 16; d >= 1; d >>= 1) {
        sq += __shfl_xor_sync(0xffffffffu, sq, d);
        sk += __shfl_xor_sync(0xffffffffu, sk, d);
    }
    const float qscale = rsqrtf(sq + 1e-6f) * 0.08838834764831845f;
    const float kscale = rsqrtf(sk + 1e-6f);
    float* qo = qn + (size_t)warp * DK + lane * 4;
    float* ko = kn + (size_t)warp * DK + lane * 4;
    *(float4*)qo = make_float4(q4.x*qscale, q4.y*qscale, q4.z*qscale, q4.w*qscale);
    *(float4*)ko = make_float4(k4.x*kscale, k4.y*kscale, k4.z*kscale, k4.w*kscale);
}

// ---------------- beta/g ----------------
__global__ void __launch_bounds__(256) betag(
    const float* __restrict__ bb, const float* __restrict__ aa,
    const float* __restrict__ A_log, const float* __restrict__ dt_bias,
    float* __restrict__ beta, float* __restrict__ g)
{
    const int i = blockIdx.x * 256 + threadIdx.x;
    const int h = i & (HV - 1);
    float bv = bb[i];
    float av = aa[i] + dt_bias[h];
    beta[i] = 1.f / (1.f + expf(-bv));
    float sp = (av > 20.f) ? av : log1pf(expf(av));
    g[i] = -expf(A_log[h]) * sp;
}

// ---------------- gated delta-rule recurrence (packed f32x2) ----------------
// grid: B*HV*2 = 128 CTAs; block 256 threads; thread owns a 32-row quarter
// column of S as 16 packed f32x2 regs. FFMA2 halves fma-pipe issue count.
__global__ void __launch_bounds__(256) recurrence(
    const float* __restrict__ qn, const float* __restrict__ kn,
    const float* __restrict__ conv, const float* __restrict__ gg,
    const float* __restrict__ bbeta, float* __restrict__ core)
{
    const int blk = blockIdx.x;
    const int b  = blk >> 6;
    const int h  = (blk >> 1) & 31;
    const int vh = blk & 1;
    const int kh = h >> 1;
    const int tid = threadIdx.x;
    const int w = tid >> 5, lane = tid & 31;
    const int q = lane >> 3;               // quarter 0..3
    const int col = vh * 64 + w * 8 + (lane & 7);
    const int pb = q * 36;                 // padded float offset of quarter

    __shared__ __align__(16) float qs[2][148];
    __shared__ __align__(16) float ks[2][148];

    ull S2[16];
    #pragma unroll
    for (int i = 0; i < 16; i++) S2[i] = 0ull;

    const bool ldr = (tid < 128);
    const int wi = ((tid >> 5) & 3) * 36 + (tid & 31);   // padded write idx for tid<128

    const float* qptr = qn + ((size_t)b * LL * HK + kh) * DK + (tid & 127);
    const float* kptr = kn + ((size_t)b * LL * HK + kh) * DK + (tid & 127);
    const float* vptr = conv + (size_t)b * LL * CONV_DIM + 2 * KEY_DIM + h * DV + col;
    const float* gptr = gg    + (size_t)b * LL * HV + h;
    const float* bptr = bbeta + (size_t)b * LL * HV + h;
    float* optr = core + ((size_t)b * LL * HV + h) * DV + col;

    float qN = 0.f, kN = 0.f;
    if (ldr) { qN = qptr[0]; kN = kptr[0]; }
    float vc = vptr[0], gc = gptr[0], bc = bptr[0];
    if (ldr) { qs[0][wi] = qN; ks[0][wi] = kN; }
    __syncthreads();

    for (int l = 0; l < LL; l++) {
        const int cur = l & 1, nxt = cur ^ 1;
        float vN = vc, gN = gc, bN = bc;
        if (l + 1 < LL) {
            size_t o = (size_t)(l + 1);
            if (ldr) {
                qN = qptr[o * (HK * DK)];
                kN = kptr[o * (HK * DK)];
            }
            vN = vptr[o * CONV_DIM];
            gN = gptr[o * HV];
            bN = bptr[o * HV];
        }

        const float eg = __expf(gc);
        const float* kcur = &ks[cur][pb];
        const float* qcur = &qs[cur][pb];

        // pass 1: kv = k . S_old (quarter partial), packed
        ull a0 = 0ull, a1 = 0ull;
        #pragma unroll
        for (int i = 0; i < 8; i++) {
            ulonglong2 kk = *(const ulonglong2*)(kcur + 4 * i);
            FMA2(a0, kk.x, S2[2*i+0], a0);
            FMA2(a1, kk.y, S2[2*i+1], a1);
        }
        ADD2(a0, a0, a1);
        float kv = lo_f(a0) + hi_f(a0);
        kv += __shfl_xor_sync(0xffffffffu, kv, 8);
        kv += __shfl_xor_sync(0xffffffffu, kv, 16);
        const float delta = (vc - eg * kv) * bc;

        // pass 2: S = eg*S + k*delta ; o = q . S (quarter partial), packed
        const ull eg2 = pack2(eg);
        const ull d2  = pack2(delta);
        ull o0 = 0ull, o1 = 0ull;
        #pragma unroll
        for (int i = 0; i < 8; i++) {
            ulonglong2 kk = *(const ulonglong2*)(kcur + 4 * i);
            ulonglong2 qq = *(const ulonglong2*)(qcur + 4 * i);
            ull t0, t1;
            MUL2(t0, kk.x, d2);
            MUL2(t1, kk.y, d2);
            FMA2(S2[2*i+0], eg2, S2[2*i+0], t0);
            FMA2(S2[2*i+1], eg2, S2[2*i+1], t1);
            FMA2(o0, qq.x, S2[2*i+0], o0);
            FMA2(o1, qq.y, S2[2*i+1], o1);
        }
        ADD2(o0, o0, o1);
        float o = lo_f(o0) + hi_f(o0);
        o += __shfl_xor_sync(0xffffffffu, o, 8);
        o += __shfl_xor_sync(0xffffffffu, o, 16);
        if (q == 0) optr[(size_t)l * VAL_DIM] = o;

        if (ldr) { qs[nxt][wi] = qN; ks[nxt][wi] = kN; }
        vc = vN; gc = gN; bc = bN;
        __syncthreads();
    }
}

// ---------------- gated RMSNorm -> bf16 hi/lo ----------------
__global__ void __launch_bounds__(256) gated_rmsnorm_split(
    const float* __restrict__ core, const float* __restrict__ z,
    const float* __restrict__ nw,
    __nv_bfloat16* __restrict__ chi, __nv_bfloat16* __restrict__ clo)
{
    const int warp = (blockIdx.x * 256 + threadIdx.x) >> 5;
    const int lane = threadIdx.x & 31;
    const size_t base = (size_t)warp * DV + lane * 4;

    float4 c4 = *(const float4*)(core + base);
    float4 z4 = *(const float4*)(z + base);
    float gx = c4.x * (z4.x / (1.f + expf(-z4.x)));
    float gy = c4.y * (z4.y / (1.f + expf(-z4.y)));
    float gz = c4.z * (z4.z / (1.f + expf(-z4.z)));
    float gw = c4.w * (z4.w / (1.f + expf(-z4.w)));
    float ss = gx*gx + gy*gy + gz*gz + gw*gw;
    #pragma unroll
    for (int d = 16; d >= 1; d >>= 1) ss += __shfl_xor_sync(0xffffffffu, ss, d);
    const float scale = rsqrtf(ss * (1.f / DV) + 1e-6f);
    float4 w4 = *(const float4*)(nw + lane * 4);
    float v0 = gx * scale * w4.x, v1 = gy * scale * w4.y;
    float v2 = gz * scale * w4.z, v3 = gw * scale * w4.w;

    __nv_bfloat16 h0 = __float2bfloat16(v0), h1 = __float2bfloat16(v1);
    __nv_bfloat16 h2 = __float2bfloat16(v2), h3 = __float2bfloat16(v3);
    __nv_bfloat162* H = (__nv_bfloat162*)(chi + base);
    __nv_bfloat162* L = (__nv_bfloat162*)(clo + base);
    H[0] = __nv_bfloat162(h0, h1);
    H[1] = __nv_bfloat162(h2, h3);
    L[0] = __nv_bfloat162(__float2bfloat16(v0 - __bfloat162float(h0)),
                          __float2bfloat16(v1 - __bfloat162float(h1)));
    L[1] = __nv_bfloat162(__float2bfloat16(v2 - __bfloat162float(h2)),
                          __float2bfloat16(v3 - __bfloat162float(h3)));
}

// ---------------- launch (stream-forked DAG, graph-capture safe) ----------------
extern "C" void kernel_launch(void* const* d_in, const int* in_sizes, int n_in,
                              void* d_out, int out_size)
{
    const float* H       = (const float*)d_in[0];
    const float* W_qkv   = (const float*)d_in[1];
    const float* W_z     = (const float*)d_in[2];
    const float* W_b     = (const float*)d_in[3];
    const float* W_a     = (const float*)d_in[4];
    const float* conv_w  = (const float*)d_in[5];
    const float* dt_bias = (const float*)d_in[6];
    const float* A_log   = (const float*)d_in[7];
    const float* norm_w  = (const float*)d_in[8];
    const float* W_out   = (const float*)d_in[9];
    float* out = (float*)d_out;

    float *mixed, *convb, *z, *core, *qn, *kn, *bb, *aa, *beta, *g;
    cudaGetSymbolAddress((void**)&mixed, g_mixed);
    cudaGetSymbolAddress((void**)&convb, g_conv);
    cudaGetSymbolAddress((void**)&z,     g_z);
    cudaGetSymbolAddress((void**)&core,  g_core);
    cudaGetSymbolAddress((void**)&qn,    g_qn);
    cudaGetSymbolAddress((void**)&kn,    g_kn);
    cudaGetSymbolAddress((void**)&bb,    g_bv);
    cudaGetSymbolAddress((void**)&aa,    g_av);
    cudaGetSymbolAddress((void**)&beta,  g_beta);
    cudaGetSymbolAddress((void**)&g,     g_g);

    __nv_bfloat16 *Hhi, *Hlo, *Wqh, *Wql, *Wzh, *Wzl, *Woh, *Wol, *chi, *clo;
    cudaGetSymbolAddress((void**)&Hhi, g_Hhi);
    cudaGetSymbolAddress((void**)&Hlo, g_Hlo);
    cudaGetSymbolAddress((void**)&Wqh, g_Wqkvt_hi);
    cudaGetSymbolAddress((void**)&Wql, g_Wqkvt_lo);
    cudaGetSymbolAddress((void**)&Wzh, g_Wzt_hi);
    cudaGetSymbolAddress((void**)&Wzl, g_Wzt_lo);
    cudaGetSymbolAddress((void**)&Woh, g_Woutt_hi);
    cudaGetSymbolAddress((void**)&Wol, g_Woutt_lo);
    cudaGetSymbolAddress((void**)&chi, g_chi);
    cudaGetSymbolAddress((void**)&clo, g_clo);

    cudaFuncSetAttribute(gemm_hmma_split, cudaFuncAttributeMaxDynamicSharedMemorySize, GSMEM);

    // lazily-created side streams/events (host resources only; no device mem)
    static cudaStream_t sA = nullptr, sB = nullptr;
    static cudaEvent_t e0 = nullptr, eSplit = nullptr, eZ = nullptr, eB2 = nullptr;
    if (!sA) {
        cudaStreamCreateWithFlags(&sA, cudaStreamNonBlocking);
        cudaStreamCreateWithFlags(&sB, cudaStreamNonBlocking);
        cudaEventCreateWithFlags(&e0,     cudaEventDisableTiming);
        cudaEventCreateWithFlags(&eSplit, cudaEventDisableTiming);
        cudaEventCreateWithFlags(&eZ,     cudaEventDisableTiming);
        cudaEventCreateWithFlags(&eB2,    cudaEventDisableTiming);
    }

    // fork origin: side streams branch off the (possibly capturing) main stream
    cudaEventRecord(e0, 0);
    cudaStreamWaitEvent(sA, e0, 0);
    cudaStreamWaitEvent(sB, e0, 0);

    // main stream: split H -> qkv weight transpose -> qkv GEMM (critical path)
    split_bf16<<<(MROWS * DD / 4) / 256, 256>>>((const float4*)H, Hhi, Hlo, MROWS * DD / 4);
    cudaEventRecord(eSplit, 0);
    transpose_split<<<dim3(CONV_DIM / 32, DD / 32), 256>>>(W_qkv, Wqh, Wql, DD, CONV_DIM);

    // stream A: z/out weight transposes, then z GEMM (overlaps recurrence later)
    transpose_split<<<dim3(VAL_DIM / 32, DD / 32), 256, 0, sA>>>(W_z, Wzh, Wzl, DD, VAL_DIM);
    transpose_split<<<dim3(DD / 32, VAL_DIM / 32), 256, 0, sA>>>(W_out, Woh, Wol, VAL_DIM, DD);
    cudaStreamWaitEvent(sA, eSplit, 0);
    gemm_hmma_split<<<dim3(VAL_DIM / 256, MROWS / 128), 256, GSMEM, sA>>>(
        Hhi, Hlo, Wzh, Wzl, z, MROWS, VAL_DIM, DD);
    cudaEventRecord(eZ, sA);

    // stream B: b/a projections + beta/g (needed before recurrence only)
    gemm_ba<<<MROWS / 8, 64, 0, sB>>>(H, W_b, W_a, bb, aa);
    betag<<<(MROWS * HV) / 256, 256, 0, sB>>>(bb, aa, A_log, dt_bias, beta, g);
    cudaEventRecord(eB2, sB);

    // main stream: qkv GEMM -> conv -> qk_norm -> recurrence
    gemm_hmma_split<<<dim3(CONV_DIM / 256, MROWS / 128), 256, GSMEM>>>(
        Hhi, Hlo, Wqh, Wql, mixed, MROWS, CONV_DIM, DD);
    conv_silu4<<<(MROWS * (size_t)CONV_DIM / 4) / 256, 256>>>(
        (const float4*)mixed, (const float4*)conv_w, (float4*)convb);
    qk_norm<<<(MROWS * HK) / 8, 256>>>(convb, qn, kn);
    cudaStreamWaitEvent(0, eB2, 0);
    recurrence<<<BB * HV * 2, 256>>>(qn, kn, convb, g, beta, core);

    // join z, then rmsnorm + out GEMM (Wout transpose ordered before eZ on sA)
    cudaStreamWaitEvent(0, eZ, 0);
    gated_rmsnorm_split<<<(MROWS * HV) / 8, 256>>>(core, z, norm_w, chi, clo);
    gemm_hmma_split<<<dim3(DD / 256, MROWS / 128), 256, GSMEM>>>(
        chi, clo, Woh, Wol, out, MROWS, DD, VAL_DIM);
}